// round 11
// baseline (speedup 1.0000x reference)
#include <cuda_runtime.h>

#define NQ      10
#define DIM     1024
#define NLAYERS 6
#define BATCH   16384

// Precomputed tables (sample-independent):
//  g_ry[l][q] = (cos θ/2, sin θ/2)
//  g_T0[idx]  = init phase pairs: (-i)^popc(n) * Dphi_0[n]
//  g_E[l-1][idx] = fused diagonal between RY layer l-1 and l
//                  (Λ-baked AND conjugated past the moved lane-ctl taus)
//  g_W[idx]   = epilogue weights (S6^{-1} and Λ_5 baked)
// idx = k*32 + lane (physical); pair covers local pack k, components 0/1.
__device__ float2 g_ry[NLAYERS][NQ];
__device__ __align__(16) float4 g_T0[512];
__device__ __align__(16) float4 g_E[5][512];
__device__ __align__(8)  float2 g_W[512];

// ---------------------------------------------------------------------------
// GF(2) algebra.
// ---------------------------------------------------------------------------
__host__ __device__ constexpr int s6inv_map(int m) {
    for (int w = 0; w < 10; ++w) {
        int cb = 9 - w, tb = 9 - ((w + 6) % 10);
        m ^= ((m >> cb) & 1) << tb;
    }
    return m;
}
__host__ __device__ constexpr int lam_after(int L, int v) {
    for (int l = 1; l <= L; ++l)
        for (int w = 0; w + l <= 4; ++w) {
            int c = 4 - w, t = 4 - w - l;
            v ^= ((v >> c) & 1) << t;
        }
    return v;
}
__host__ __device__ constexpr int inv_mask(int L, int b) {
    for (int v = 1; v < 32; ++v)
        if (lam_after(L, v) == (1 << b)) return v;
    return 0;
}
__host__ __device__ constexpr int row_mask(int L, int b) {
    int r = 0;
    for (int j = 0; j < 5; ++j)
        r |= ((lam_after(L, 1 << j) >> b) & 1) << j;
    return r;
}

// ---------------------------------------------------------------------------
// Packed f32x2 helpers (SASS FFMA2/FMUL2 — ptxas never emits these from C++)
// ---------------------------------------------------------------------------
__device__ __forceinline__ float2 ffma2_(float2 a, float2 b, float2 c) {
    float2 d;
    asm("{\n\t.reg .b64 A,B,C,D;\n\t"
        "mov.b64 A,{%2,%3};\n\t mov.b64 B,{%4,%5};\n\t mov.b64 C,{%6,%7};\n\t"
        "fma.rn.f32x2 D,A,B,C;\n\t"
        "mov.b64 {%0,%1},D;\n\t}"
        : "=f"(d.x), "=f"(d.y)
        : "f"(a.x), "f"(a.y), "f"(b.x), "f"(b.y), "f"(c.x), "f"(c.y));
    return d;
}
__device__ __forceinline__ float2 fmul2_(float2 a, float2 b) {
    float2 d;
    asm("{\n\t.reg .b64 A,B,D;\n\t"
        "mov.b64 A,{%2,%3};\n\t mov.b64 B,{%4,%5};\n\t"
        "mul.rn.f32x2 D,A,B;\n\t"
        "mov.b64 {%0,%1},D;\n\t}"
        : "=f"(d.x), "=f"(d.y)
        : "f"(a.x), "f"(a.y), "f"(b.x), "f"(b.y));
    return d;
}
__device__ __forceinline__ float2 fsub2_(float2 a, float2 b) {
    float2 d;
    asm("{\n\t.reg .b64 A,B,D;\n\t"
        "mov.b64 A,{%2,%3};\n\t mov.b64 B,{%4,%5};\n\t"
        "sub.rn.f32x2 D,A,B;\n\t"
        "mov.b64 {%0,%1},D;\n\t}"
        : "=f"(d.x), "=f"(d.y)
        : "f"(a.x), "f"(a.y), "f"(b.x), "f"(b.y));
    return d;
}
__device__ __forceinline__ float2 bc2(float v) { return make_float2(v, v); }

// ---------------------------------------------------------------------------
// Pre-kernel: one job per block. Job 0: g_ry + T0; jobs 1..5: E_l; job 6: W.
// ---------------------------------------------------------------------------
__device__ __forceinline__ float sum_signed(int n, const float* ql, int l, int off) {
    float a = 0.f;
    #pragma unroll
    for (int q = 0; q < NQ; ++q) {
        float v = ql[(l * NQ + q) * 3 + off];
        a += ((n >> (9 - q)) & 1) ? v : -v;
    }
    return 0.5f * a;
}

__global__ void table_kernel(const float* __restrict__ ql,
                             const float* __restrict__ fcw) {
    const int idx = threadIdx.x;      // 0..511
    const int job = blockIdx.x;       // 0..6
    const int k = idx >> 5, lane = idx & 31;

    if (job == 0) {
        if (idx < NLAYERS * NQ) {
            int l = idx / NQ, q = idx % NQ;
            float s, c; sincosf(0.5f * ql[(l * NQ + q) * 3 + 1], &s, &c);
            g_ry[l][q] = make_float2(c, s);
        }
        // T0 (Λ = identity): (-i)^popc(n) * Dphi_0[n]
        float cs[2], sn[2];
        #pragma unroll
        for (int comp = 0; comp < 2; ++comp) {
            int n = (lane << 5) | (k << 1) | comp;
            float ang = -1.57079632679f * __popc(n) + sum_signed(n, ql, 0, 0);
            sincosf(ang, &sn[comp], &cs[comp]);
        }
        g_T0[idx] = make_float4(cs[0], sn[0], cs[1], sn[1]);
    } else if (job <= 5) {
        // E_l, Λ_{l-1}-baked, conjugated past the moved lane-ctl taus of
        // block l: E'[p,j] = E[p, j ^ f(p)].
        const int l = job;
        int llog = lam_after(l - 1, lane);
        int f = 0;
        for (int w = 5 - l; w <= 4; ++w)
            if (__popc(lane & row_mask(l, 4 - w)) & 1) f ^= 1 << (9 - w - l);
        float cs[2], sn[2];
        #pragma unroll
        for (int comp = 0; comp < 2; ++comp) {
            int n = ((llog << 5) | (k << 1) | comp) ^ f;
            float angw = sum_signed(n, ql, l - 1, 2);
            int p = n;             // sigma^{-1}: apply tau_0 .. tau_9 in order
            #pragma unroll
            for (int w = 0; w < NQ; ++w) {
                int cbit = 9 - w;
                int tbit = 9 - ((w + l) % NQ);
                p ^= ((p >> cbit) & 1) << tbit;
            }
            float angp = sum_signed(p, ql, l, 0);
            sincosf(angw + angp, &sn[comp], &cs[comp]);
        }
        g_E[l - 1][idx] = make_float4(cs[0], sn[0], cs[1], sn[1]);
    } else {
        // Epilogue weights with Λ_5 and S6^{-1} baked.
        int llog = lam_after(5, lane);
        float wv[2];
        #pragma unroll
        for (int comp = 0; comp < 2; ++comp) {
            int n = (llog << 5) | (k << 1) | comp;
            int p = s6inv_map(n);
            float a = 0.f;
            #pragma unroll
            for (int q = 0; q < NQ; ++q) {
                float v = fcw[q];
                a += ((p >> (9 - q)) & 1) ? -v : v;
            }
            wv[comp] = a;
        }
        g_W[idx] = make_float2(wv[0], wv[1]);
    }
}

// ---------------------------------------------------------------------------
// State layout: logical amplitude n: bits 9..5 lane (via Λ), 4..1 pack k,
// 0 comp. Qubit q acts on logical bit 9-q.
// ---------------------------------------------------------------------------

// RY gate on logical lane-space bit B5 (layer-block context L for Λ).
template<int L, int B5>
__device__ __forceinline__ void ry_lane_gate(float2 sr[16], float2 si[16], int lane,
                                             float2 g) {
    constexpr unsigned msk = (unsigned)inv_mask(L, B5);
    constexpr int row = row_mask(L, B5);
    const bool hi = __popc(lane & row) & 1;
    const float2 c2 = bc2(g.x);
    const float2 s2 = bc2(hi ? g.y : -g.y);
    #pragma unroll
    for (int k = 0; k < 16; ++k) {
        float2 qr, qi;
        qr.x = __shfl_xor_sync(0xffffffffu, sr[k].x, msk);
        qr.y = __shfl_xor_sync(0xffffffffu, sr[k].y, msk);
        qi.x = __shfl_xor_sync(0xffffffffu, si[k].x, msk);
        qi.y = __shfl_xor_sync(0xffffffffu, si[k].y, msk);
        sr[k] = ffma2_(s2, qr, fmul2_(c2, sr[k]));
        si[k] = ffma2_(s2, qi, fmul2_(c2, si[k]));
    }
}

// Plain RY gate on local bit B (1..4 = pack bit B-1; 0 = comp bit).
template<int B>
__device__ __forceinline__ void ry_local_gate(float2 sr[16], float2 si[16], float2 g) {
    if constexpr (B >= 1) {
        constexpr int pb = B - 1;
        const float2 cl2 = bc2(g.x), sl2 = bc2(g.y), nsl2 = bc2(-g.y);
        #pragma unroll
        for (int t = 0; t < 8; ++t) {
            const int k  = ((t >> pb) << (pb + 1)) | (t & ((1 << pb) - 1));
            const int k2 = k | (1 << pb);
            float2 Ar = sr[k], Ai = si[k], Br = sr[k2], Bi = si[k2];
            sr[k]  = ffma2_(nsl2, Br, fmul2_(cl2, Ar));
            si[k]  = ffma2_(nsl2, Bi, fmul2_(cl2, Ai));
            sr[k2] = ffma2_(cl2, Br, fmul2_(sl2, Ar));
            si[k2] = ffma2_(cl2, Bi, fmul2_(sl2, Ai));
        }
    } else {
        const float2 c2 = bc2(g.x);
        const float2 sp2 = make_float2(-g.y, g.y);
        #pragma unroll
        for (int k = 0; k < 16; ++k) {
            float2 vr = sr[k], vi = si[k];
            float2 wr = make_float2(vr.y, vr.x);
            float2 wi = make_float2(vi.y, vi.x);
            sr[k] = ffma2_(sp2, wr, fmul2_(c2, vr));
            si[k] = ffma2_(sp2, wi, fmul2_(c2, vi));
        }
    }
}

// RY local gate on bit B, fused with a FOLLOWING lane-ctl CNOT from block J+1.
template<int J, int B>
__device__ __forceinline__ void ry_local_gate_fused(float2 sr[16], float2 si[16],
                                                    int lane, float2 g) {
    constexpr int row = row_mask(J + 1, B + J - 4);
    const bool ctl = __popc(lane & row) & 1;
    const float cl = g.x, sl = g.y;
    if constexpr (B >= 1) {
        constexpr int pb = B - 1;
        const float2 a1 = bc2(ctl ? sl :  cl);
        const float2 b1 = bc2(ctl ? cl : -sl);
        const float2 a2 = bc2(ctl ? cl :  sl);
        const float2 b2 = bc2(ctl ? -sl : cl);
        #pragma unroll
        for (int t = 0; t < 8; ++t) {
            const int k  = ((t >> pb) << (pb + 1)) | (t & ((1 << pb) - 1));
            const int k2 = k | (1 << pb);
            float2 Ar = sr[k], Ai = si[k], Br = sr[k2], Bi = si[k2];
            sr[k]  = ffma2_(b1, Br, fmul2_(a1, Ar));
            si[k]  = ffma2_(b1, Bi, fmul2_(a1, Ai));
            sr[k2] = ffma2_(b2, Br, fmul2_(a2, Ar));
            si[k2] = ffma2_(b2, Bi, fmul2_(a2, Ai));
        }
    } else {
        const float2 c2  = make_float2(ctl ? sl :  cl, ctl ? -sl : cl);
        const float2 sp2 = make_float2(ctl ? cl : -sl, ctl ?  cl : sl);
        #pragma unroll
        for (int k = 0; k < 16; ++k) {
            float2 vr = sr[k], vi = si[k];
            float2 wr = make_float2(vr.y, vr.x);
            float2 wi = make_float2(vi.y, vi.x);
            sr[k] = ffma2_(sp2, wr, fmul2_(c2, vr));
            si[k] = ffma2_(sp2, wi, fmul2_(c2, vi));
        }
    }
}

// Fused stage: CNOT(local control bit Bc -> logical lane bit B5) + RY(target).
template<int L, int Bc, int B5>
__device__ __forceinline__ void fused_cnot_ry(float2 sr[16], float2 si[16], int lane,
                                              float2 g) {
    constexpr unsigned msk = (unsigned)inv_mask(L, B5);
    constexpr int row = row_mask(L, B5);
    const bool hi = __popc(lane & row) & 1;
    const float sg = hi ? g.y : -g.y;
    if constexpr (Bc == 0) {
        const float2 A = make_float2(g.x, sg);
        const float2 B = make_float2(sg, g.x);
        #pragma unroll
        for (int k = 0; k < 16; ++k) {
            float2 qr, qi;
            qr.x = __shfl_xor_sync(0xffffffffu, sr[k].x, msk);
            qr.y = __shfl_xor_sync(0xffffffffu, sr[k].y, msk);
            qi.x = __shfl_xor_sync(0xffffffffu, si[k].x, msk);
            qi.y = __shfl_xor_sync(0xffffffffu, si[k].y, msk);
            sr[k] = ffma2_(B, qr, fmul2_(A, sr[k]));
            si[k] = ffma2_(B, qi, fmul2_(A, si[k]));
        }
    } else {
        const float2 c2 = bc2(g.x), s2 = bc2(sg);
        #pragma unroll
        for (int k = 0; k < 16; ++k) {
            float2 qr, qi;
            qr.x = __shfl_xor_sync(0xffffffffu, sr[k].x, msk);
            qr.y = __shfl_xor_sync(0xffffffffu, sr[k].y, msk);
            qi.x = __shfl_xor_sync(0xffffffffu, si[k].x, msk);
            qi.y = __shfl_xor_sync(0xffffffffu, si[k].y, msk);
            const bool ctl = (k >> (Bc - 1)) & 1;       // compile-time after unroll
            const float2 A = ctl ? s2 : c2;
            const float2 B = ctl ? c2 : s2;
            sr[k] = ffma2_(B, qr, fmul2_(A, sr[k]));
            si[k] = ffma2_(B, qi, fmul2_(A, si[k]));
        }
    }
}

// ---------------------------------------------------------------------------
// Standalone CNOT: local control bit BC (>=1), local/comp target BT.
// ---------------------------------------------------------------------------
template<int L, int BC, int BT>
__device__ __forceinline__ void cnot_gate(float2 sr[16], float2 si[16], int lane) {
    if constexpr (BC >= 1 && BT >= 1) {
        constexpr int pbc = BC - 1, pbt = BT - 1;
        #pragma unroll
        for (int k = 0; k < 16; ++k) {
            if (((k >> pbc) & 1) && !((k >> pbt) & 1)) {
                const int k2 = k | (1 << pbt);
                float2 t;
                t = sr[k]; sr[k] = sr[k2]; sr[k2] = t;
                t = si[k]; si[k] = si[k2]; si[k2] = t;
            }
        }
    } else {   // BC >= 1, BT == 0
        constexpr int pb = BC - 1;
        #pragma unroll
        for (int k = 0; k < 16; ++k) {
            if ((k >> pb) & 1) {
                float t;
                t = sr[k].x; sr[k].x = sr[k].y; sr[k].y = t;
                t = si[k].x; si[k].x = si[k].y; si[k].y = t;
            }
        }
    }
}

// fused diagonal: per pack complex multiply by table phase, 1-ahead prefetch
__device__ __forceinline__ void apply_diag(float2 sr[16], float2 si[16], int lane,
                                           const float4* __restrict__ tbl) {
    float4 t = __ldg(tbl + lane);
    #pragma unroll
    for (int k = 0; k < 16; ++k) {
        float4 cur = t;
        if (k < 15) t = __ldg(tbl + (k + 1) * 32 + lane);
        float2 c = make_float2(cur.x, cur.z);
        float2 s = make_float2(cur.y, cur.w);
        float2 r = sr[k], i = si[k];
        sr[k] = fsub2_(fmul2_(c, r), fmul2_(s, i));
        si[k] = ffma2_(c, i, fmul2_(s, r));
    }
}

// ---------------------------------------------------------------------------
// Block L (shift r = L):
//  1. (moved lane-ctl taus of this block already executed inside layer L-1)
//  2. diag E_L (table conjugated accordingly)
//  3. lane/lane taus: DEFERRED into Λ (free)
//  4. standalone local/local taus w = 5..9-L (register renaming, ~free)
//  5. fused stages w = 10-L..9: CNOT(local ctl -> lane tgt) + RY
//  6. remaining RY gates q = L..9; local gates on bits B >= 4-L carry the
//     fused lane-ctl tau of block L+1.
// ---------------------------------------------------------------------------
template<int L, int W>
__device__ __forceinline__ void standalone_taus(float2 sr[16], float2 si[16], int lane) {
    if constexpr (W <= 9 - L) {
        cnot_gate<L, 9 - W, 9 - W - L>(sr, si, lane);
        standalone_taus<L, W + 1>(sr, si, lane);
    }
}
template<int L, int W>
__device__ __forceinline__ void fused_stages(float2 sr[16], float2 si[16], int lane,
                                             const float2* __restrict__ ry) {
    if constexpr (W <= 9) {
        constexpr int Bc = 9 - W;          // local control bit (0..L-1)
        constexpr int B5 = 14 - W - L;     // logical lane-space target bit (0..4)
        fused_cnot_ry<L, Bc, B5>(sr, si, lane, __ldg(ry + (W + L - 10)));
        fused_stages<L, W + 1>(sr, si, lane, ry);
    }
}
template<int L, int Q>
__device__ __forceinline__ void remaining_gates(float2 sr[16], float2 si[16], int lane,
                                                const float2* __restrict__ ry) {
    if constexpr (Q <= 9) {
        if constexpr (Q <= 4) {
            ry_lane_gate<L, 4 - Q>(sr, si, lane, __ldg(ry + Q));
        } else {
            constexpr int B = 9 - Q;
            if constexpr (L <= 4 && B >= 4 - L)
                ry_local_gate_fused<L, B>(sr, si, lane, __ldg(ry + Q));
            else
                ry_local_gate<B>(sr, si, __ldg(ry + Q));
        }
        remaining_gates<L, Q + 1>(sr, si, lane, ry);
    }
}
template<int L>
__device__ __forceinline__ void fused_layer(float2 sr[16], float2 si[16], int lane) {
    apply_diag(sr, si, lane, g_E[L - 1]);
    standalone_taus<L, 5>(sr, si, lane);       // local/local only
    fused_stages<L, 10 - L>(sr, si, lane, g_ry[L]);
    remaining_gates<L, L>(sr, si, lane, g_ry[L]);
}

// ---------------------------------------------------------------------------
// Main kernel: one warp per sample; 256 thr, 2 CTAs/SM (128 regs, no spill).
// ---------------------------------------------------------------------------
__global__ void __launch_bounds__(256, 2) qcnn_kernel(
    const float* __restrict__ x,
    const float* __restrict__ fc_b,
    float* __restrict__ out)
{
    const int warp = (blockIdx.x * blockDim.x + threadIdx.x) >> 5;
    const int lane = threadIdx.x & 31;
    if (warp >= BATCH) return;

    // --- initial product state magnitudes (Λ = identity here) ---------------
    const float* xb = x + warp * NQ;
    float cq[NQ], sq[NQ];
    #pragma unroll
    for (int q = 0; q < NQ; ++q) {
        float h = 0.5f * __ldg(xb + q);
        sincosf(h, &sq[q], &cq[q]);
    }
    float A = 1.f;
    #pragma unroll
    for (int q = 0; q < 5; ++q)
        A *= ((lane >> (4 - q)) & 1) ? sq[q] : cq[q];

    float m[16];
    m[0] = A;
    #pragma unroll
    for (int t = 0; t < 4; ++t) {
        const int q = 8 - t;
        const int sz = 1 << t;
        #pragma unroll
        for (int k = sz - 1; k >= 0; --k) {
            float v = m[k];
            m[k + sz] = v * sq[q];
            m[k]      = v * cq[q];
        }
    }
    float2 sr[16], si[16];
    #pragma unroll
    for (int k = 0; k < 16; ++k) {
        float4 t = __ldg(&g_T0[k * 32 + lane]);
        float2 mag2 = make_float2(m[k] * cq[9], m[k] * sq[9]);
        sr[k] = fmul2_(mag2, make_float2(t.x, t.z));
        si[k] = fmul2_(mag2, make_float2(t.y, t.w));
    }

    // --- circuit -------------------------------------------------------------
    remaining_gates<0, 0>(sr, si, lane, g_ry[0]);   // Y_0 (+ fused tau of block 1)
    fused_layer<1>(sr, si, lane);
    fused_layer<2>(sr, si, lane);
    fused_layer<3>(sr, si, lane);
    fused_layer<4>(sr, si, lane);
    fused_layer<5>(sr, si, lane);
    // P_5 (r=6) and Λ_5 fully virtualized into the epilogue weight table.

    // --- epilogue: out = sum_m w_m |psi_m|^2, w from precomputed table -------
    float2 acc2 = make_float2(0.f, 0.f);
    #pragma unroll
    for (int k = 0; k < 16; ++k) {
        float2 w2 = __ldg(&g_W[k * 32 + lane]);
        float2 p2 = ffma2_(si[k], si[k], fmul2_(sr[k], sr[k]));
        acc2 = ffma2_(w2, p2, acc2);
    }
    float acc = acc2.x + acc2.y;
    #pragma unroll
    for (int off = 16; off; off >>= 1)
        acc += __shfl_xor_sync(0xffffffffu, acc, off);

    if (lane == 0) out[warp] = acc + __ldg(fc_b);
}

// ---------------------------------------------------------------------------
extern "C" void kernel_launch(void* const* d_in, const int* in_sizes, int n_in,
                              void* d_out, int out_size) {
    const float* x    = (const float*)d_in[0];   // (16384, 10)
    const float* ql   = (const float*)d_in[1];   // (6, 10, 3)
    const float* fcw  = (const float*)d_in[2];   // (1, 10)
    const float* fcb  = (const float*)d_in[3];   // (1,)
    float* out = (float*)d_out;                  // (16384, 1)

    table_kernel<<<7, 512>>>(ql, fcw);
    qcnn_kernel<<<BATCH / 8, 256>>>(x, fcb, out);
}

// round 12
// speedup vs baseline: 1.6231x; 1.6231x over previous
#include <cuda_runtime.h>

#define NQ      10
#define DIM     1024
#define NLAYERS 6
#define BATCH   16384

// Precomputed tables (sample-independent):
//  g_ry[l][q] = (cos θ/2, sin θ/2)
//  g_T0[idx]  = init phase pairs: (-i)^popc(n) * Dphi_0[n]
//  g_E[l-1][idx] = fused diagonal between RY layer l-1 and l
//                  (Λ-baked AND conjugated past the moved lane-ctl taus)
//  g_W[idx]   = epilogue weights (S6^{-1} and Λ_5 baked)
// idx = k*32 + lane (physical); pair covers local pack k, components 0/1.
__device__ float2 g_ry[NLAYERS][NQ];
__device__ __align__(16) float4 g_T0[512];
__device__ __align__(16) float4 g_E[5][512];
__device__ __align__(8)  float2 g_W[512];

// ---------------------------------------------------------------------------
// GF(2) algebra.
// ---------------------------------------------------------------------------
__host__ __device__ constexpr int s6inv_map(int m) {
    for (int w = 0; w < 10; ++w) {
        int cb = 9 - w, tb = 9 - ((w + 6) % 10);
        m ^= ((m >> cb) & 1) << tb;
    }
    return m;
}
__host__ __device__ constexpr int lam_after(int L, int v) {
    for (int l = 1; l <= L; ++l)
        for (int w = 0; w + l <= 4; ++w) {
            int c = 4 - w, t = 4 - w - l;
            v ^= ((v >> c) & 1) << t;
        }
    return v;
}
__host__ __device__ constexpr int inv_mask(int L, int b) {
    for (int v = 1; v < 32; ++v)
        if (lam_after(L, v) == (1 << b)) return v;
    return 0;
}
__host__ __device__ constexpr int row_mask(int L, int b) {
    int r = 0;
    for (int j = 0; j < 5; ++j)
        r |= ((lam_after(L, 1 << j) >> b) & 1) << j;
    return r;
}

// ---------------------------------------------------------------------------
// Packed f32x2 helpers (SASS FFMA2/FMUL2 — ptxas never emits these from C++)
// ---------------------------------------------------------------------------
__device__ __forceinline__ float2 ffma2_(float2 a, float2 b, float2 c) {
    float2 d;
    asm("{\n\t.reg .b64 A,B,C,D;\n\t"
        "mov.b64 A,{%2,%3};\n\t mov.b64 B,{%4,%5};\n\t mov.b64 C,{%6,%7};\n\t"
        "fma.rn.f32x2 D,A,B,C;\n\t"
        "mov.b64 {%0,%1},D;\n\t}"
        : "=f"(d.x), "=f"(d.y)
        : "f"(a.x), "f"(a.y), "f"(b.x), "f"(b.y), "f"(c.x), "f"(c.y));
    return d;
}
__device__ __forceinline__ float2 fmul2_(float2 a, float2 b) {
    float2 d;
    asm("{\n\t.reg .b64 A,B,D;\n\t"
        "mov.b64 A,{%2,%3};\n\t mov.b64 B,{%4,%5};\n\t"
        "mul.rn.f32x2 D,A,B;\n\t"
        "mov.b64 {%0,%1},D;\n\t}"
        : "=f"(d.x), "=f"(d.y)
        : "f"(a.x), "f"(a.y), "f"(b.x), "f"(b.y));
    return d;
}
__device__ __forceinline__ float2 fsub2_(float2 a, float2 b) {
    float2 d;
    asm("{\n\t.reg .b64 A,B,D;\n\t"
        "mov.b64 A,{%2,%3};\n\t mov.b64 B,{%4,%5};\n\t"
        "sub.rn.f32x2 D,A,B;\n\t"
        "mov.b64 {%0,%1},D;\n\t}"
        : "=f"(d.x), "=f"(d.y)
        : "f"(a.x), "f"(a.y), "f"(b.x), "f"(b.y));
    return d;
}
__device__ __forceinline__ float2 bc2(float v) { return make_float2(v, v); }

// ---------------------------------------------------------------------------
// Pre-kernel: one job per block. Job 0: g_ry + T0; jobs 1..5: E_l; job 6: W.
// ---------------------------------------------------------------------------
__device__ __forceinline__ float sum_signed(int n, const float* ql, int l, int off) {
    float a = 0.f;
    #pragma unroll
    for (int q = 0; q < NQ; ++q) {
        float v = ql[(l * NQ + q) * 3 + off];
        a += ((n >> (9 - q)) & 1) ? v : -v;
    }
    return 0.5f * a;
}

__global__ void table_kernel(const float* __restrict__ ql,
                             const float* __restrict__ fcw) {
    const int idx = threadIdx.x;      // 0..511
    const int job = blockIdx.x;       // 0..6
    const int k = idx >> 5, lane = idx & 31;

    if (job == 0) {
        if (idx < NLAYERS * NQ) {
            int l = idx / NQ, q = idx % NQ;
            float s, c; sincosf(0.5f * ql[(l * NQ + q) * 3 + 1], &s, &c);
            g_ry[l][q] = make_float2(c, s);
        }
        // T0 (Λ = identity): (-i)^popc(n) * Dphi_0[n]
        float cs[2], sn[2];
        #pragma unroll
        for (int comp = 0; comp < 2; ++comp) {
            int n = (lane << 5) | (k << 1) | comp;
            float ang = -1.57079632679f * __popc(n) + sum_signed(n, ql, 0, 0);
            sincosf(ang, &sn[comp], &cs[comp]);
        }
        g_T0[idx] = make_float4(cs[0], sn[0], cs[1], sn[1]);
    } else if (job <= 5) {
        // E_l, Λ_{l-1}-baked, conjugated past the moved lane-ctl taus of
        // block l: E'[p,j] = E[p, j ^ f(p)].
        const int l = job;
        int llog = lam_after(l - 1, lane);
        int f = 0;
        for (int w = 5 - l; w <= 4; ++w)
            if (__popc(lane & row_mask(l, 4 - w)) & 1) f ^= 1 << (9 - w - l);
        float cs[2], sn[2];
        #pragma unroll
        for (int comp = 0; comp < 2; ++comp) {
            int n = ((llog << 5) | (k << 1) | comp) ^ f;
            float angw = sum_signed(n, ql, l - 1, 2);
            int p = n;             // sigma^{-1}: apply tau_0 .. tau_9 in order
            #pragma unroll
            for (int w = 0; w < NQ; ++w) {
                int cbit = 9 - w;
                int tbit = 9 - ((w + l) % NQ);
                p ^= ((p >> cbit) & 1) << tbit;
            }
            float angp = sum_signed(p, ql, l, 0);
            sincosf(angw + angp, &sn[comp], &cs[comp]);
        }
        g_E[l - 1][idx] = make_float4(cs[0], sn[0], cs[1], sn[1]);
    } else {
        // Epilogue weights with Λ_5 and S6^{-1} baked.
        int llog = lam_after(5, lane);
        float wv[2];
        #pragma unroll
        for (int comp = 0; comp < 2; ++comp) {
            int n = (llog << 5) | (k << 1) | comp;
            int p = s6inv_map(n);
            float a = 0.f;
            #pragma unroll
            for (int q = 0; q < NQ; ++q) {
                float v = fcw[q];
                a += ((p >> (9 - q)) & 1) ? -v : v;
            }
            wv[comp] = a;
        }
        g_W[idx] = make_float2(wv[0], wv[1]);
    }
}

// ---------------------------------------------------------------------------
// State layout: logical amplitude n: bits 9..5 lane (via Λ), 4..1 pack k,
// 0 comp. Qubit q acts on logical bit 9-q.
// ---------------------------------------------------------------------------

// RY gate on logical lane-space bit B5 (layer-block context L for Λ).
template<int L, int B5>
__device__ __forceinline__ void ry_lane_gate(float2 sr[16], float2 si[16], int lane,
                                             float2 g) {
    constexpr unsigned msk = (unsigned)inv_mask(L, B5);
    constexpr int row = row_mask(L, B5);
    const bool hi = __popc(lane & row) & 1;
    const float2 c2 = bc2(g.x);
    const float2 s2 = bc2(hi ? g.y : -g.y);
    #pragma unroll
    for (int k = 0; k < 16; ++k) {
        float2 qr, qi;
        qr.x = __shfl_xor_sync(0xffffffffu, sr[k].x, msk);
        qr.y = __shfl_xor_sync(0xffffffffu, sr[k].y, msk);
        qi.x = __shfl_xor_sync(0xffffffffu, si[k].x, msk);
        qi.y = __shfl_xor_sync(0xffffffffu, si[k].y, msk);
        sr[k] = ffma2_(s2, qr, fmul2_(c2, sr[k]));
        si[k] = ffma2_(s2, qi, fmul2_(c2, si[k]));
    }
}

// Plain RY gate on local bit B (1..4 = pack bit B-1; 0 = comp bit).
template<int B>
__device__ __forceinline__ void ry_local_gate(float2 sr[16], float2 si[16], float2 g) {
    if constexpr (B >= 1) {
        constexpr int pb = B - 1;
        const float2 cl2 = bc2(g.x), sl2 = bc2(g.y), nsl2 = bc2(-g.y);
        #pragma unroll
        for (int t = 0; t < 8; ++t) {
            const int k  = ((t >> pb) << (pb + 1)) | (t & ((1 << pb) - 1));
            const int k2 = k | (1 << pb);
            float2 Ar = sr[k], Ai = si[k], Br = sr[k2], Bi = si[k2];
            sr[k]  = ffma2_(nsl2, Br, fmul2_(cl2, Ar));
            si[k]  = ffma2_(nsl2, Bi, fmul2_(cl2, Ai));
            sr[k2] = ffma2_(cl2, Br, fmul2_(sl2, Ar));
            si[k2] = ffma2_(cl2, Bi, fmul2_(sl2, Ai));
        }
    } else {
        const float2 c2 = bc2(g.x);
        const float2 sp2 = make_float2(-g.y, g.y);
        #pragma unroll
        for (int k = 0; k < 16; ++k) {
            float2 vr = sr[k], vi = si[k];
            float2 wr = make_float2(vr.y, vr.x);
            float2 wi = make_float2(vi.y, vi.x);
            sr[k] = ffma2_(sp2, wr, fmul2_(c2, vr));
            si[k] = ffma2_(sp2, wi, fmul2_(c2, vi));
        }
    }
}

// RY local gate on bit B, fused with a FOLLOWING lane-ctl CNOT from block J+1.
template<int J, int B>
__device__ __forceinline__ void ry_local_gate_fused(float2 sr[16], float2 si[16],
                                                    int lane, float2 g) {
    constexpr int row = row_mask(J + 1, B + J - 4);
    const bool ctl = __popc(lane & row) & 1;
    const float cl = g.x, sl = g.y;
    if constexpr (B >= 1) {
        constexpr int pb = B - 1;
        const float2 a1 = bc2(ctl ? sl :  cl);
        const float2 b1 = bc2(ctl ? cl : -sl);
        const float2 a2 = bc2(ctl ? cl :  sl);
        const float2 b2 = bc2(ctl ? -sl : cl);
        #pragma unroll
        for (int t = 0; t < 8; ++t) {
            const int k  = ((t >> pb) << (pb + 1)) | (t & ((1 << pb) - 1));
            const int k2 = k | (1 << pb);
            float2 Ar = sr[k], Ai = si[k], Br = sr[k2], Bi = si[k2];
            sr[k]  = ffma2_(b1, Br, fmul2_(a1, Ar));
            si[k]  = ffma2_(b1, Bi, fmul2_(a1, Ai));
            sr[k2] = ffma2_(b2, Br, fmul2_(a2, Ar));
            si[k2] = ffma2_(b2, Bi, fmul2_(a2, Ai));
        }
    } else {
        const float2 c2  = make_float2(ctl ? sl :  cl, ctl ? -sl : cl);
        const float2 sp2 = make_float2(ctl ? cl : -sl, ctl ?  cl : sl);
        #pragma unroll
        for (int k = 0; k < 16; ++k) {
            float2 vr = sr[k], vi = si[k];
            float2 wr = make_float2(vr.y, vr.x);
            float2 wi = make_float2(vi.y, vi.x);
            sr[k] = ffma2_(sp2, wr, fmul2_(c2, vr));
            si[k] = ffma2_(sp2, wi, fmul2_(c2, vi));
        }
    }
}

// Fused stage: CNOT(local control bit Bc -> logical lane bit B5) + RY(target).
template<int L, int Bc, int B5>
__device__ __forceinline__ void fused_cnot_ry(float2 sr[16], float2 si[16], int lane,
                                              float2 g) {
    constexpr unsigned msk = (unsigned)inv_mask(L, B5);
    constexpr int row = row_mask(L, B5);
    const bool hi = __popc(lane & row) & 1;
    const float sg = hi ? g.y : -g.y;
    if constexpr (Bc == 0) {
        const float2 A = make_float2(g.x, sg);
        const float2 B = make_float2(sg, g.x);
        #pragma unroll
        for (int k = 0; k < 16; ++k) {
            float2 qr, qi;
            qr.x = __shfl_xor_sync(0xffffffffu, sr[k].x, msk);
            qr.y = __shfl_xor_sync(0xffffffffu, sr[k].y, msk);
            qi.x = __shfl_xor_sync(0xffffffffu, si[k].x, msk);
            qi.y = __shfl_xor_sync(0xffffffffu, si[k].y, msk);
            sr[k] = ffma2_(B, qr, fmul2_(A, sr[k]));
            si[k] = ffma2_(B, qi, fmul2_(A, si[k]));
        }
    } else {
        const float2 c2 = bc2(g.x), s2 = bc2(sg);
        #pragma unroll
        for (int k = 0; k < 16; ++k) {
            float2 qr, qi;
            qr.x = __shfl_xor_sync(0xffffffffu, sr[k].x, msk);
            qr.y = __shfl_xor_sync(0xffffffffu, sr[k].y, msk);
            qi.x = __shfl_xor_sync(0xffffffffu, si[k].x, msk);
            qi.y = __shfl_xor_sync(0xffffffffu, si[k].y, msk);
            const bool ctl = (k >> (Bc - 1)) & 1;       // compile-time after unroll
            const float2 A = ctl ? s2 : c2;
            const float2 B = ctl ? c2 : s2;
            sr[k] = ffma2_(B, qr, fmul2_(A, sr[k]));
            si[k] = ffma2_(B, qi, fmul2_(A, si[k]));
        }
    }
}

// ---------------------------------------------------------------------------
// Standalone CNOT: local control bit BC (>=1), local/comp target BT.
// ---------------------------------------------------------------------------
template<int L, int BC, int BT>
__device__ __forceinline__ void cnot_gate(float2 sr[16], float2 si[16], int lane) {
    if constexpr (BC >= 1 && BT >= 1) {
        constexpr int pbc = BC - 1, pbt = BT - 1;
        #pragma unroll
        for (int k = 0; k < 16; ++k) {
            if (((k >> pbc) & 1) && !((k >> pbt) & 1)) {
                const int k2 = k | (1 << pbt);
                float2 t;
                t = sr[k]; sr[k] = sr[k2]; sr[k2] = t;
                t = si[k]; si[k] = si[k2]; si[k2] = t;
            }
        }
    } else {   // BC >= 1, BT == 0
        constexpr int pb = BC - 1;
        #pragma unroll
        for (int k = 0; k < 16; ++k) {
            if ((k >> pb) & 1) {
                float t;
                t = sr[k].x; sr[k].x = sr[k].y; sr[k].y = t;
                t = si[k].x; si[k].x = si[k].y; si[k].y = t;
            }
        }
    }
}

// fused diagonal: per pack complex multiply by table phase.
// 16 INDEPENDENT __ldg's — ptxas front-batches them (MLP ~16). Do NOT chain
// them through one register ("prefetch"): that serializes the loads (R11).
__device__ __forceinline__ void apply_diag(float2 sr[16], float2 si[16], int lane,
                                           const float4* __restrict__ tbl) {
    #pragma unroll
    for (int k = 0; k < 16; ++k) {
        float4 t = __ldg(tbl + k * 32 + lane);
        float2 c = make_float2(t.x, t.z);
        float2 s = make_float2(t.y, t.w);
        float2 r = sr[k], i = si[k];
        sr[k] = fsub2_(fmul2_(c, r), fmul2_(s, i));
        si[k] = ffma2_(c, i, fmul2_(s, r));
    }
}

// ---------------------------------------------------------------------------
// Block L (shift r = L):
//  1. (moved lane-ctl taus of this block already executed inside layer L-1)
//  2. diag E_L (table conjugated accordingly)
//  3. lane/lane taus: DEFERRED into Λ (free)
//  4. standalone local/local taus w = 5..9-L (register renaming, ~free)
//  5. fused stages w = 10-L..9: CNOT(local ctl -> lane tgt) + RY
//  6. remaining RY gates q = L..9; local gates on bits B >= 4-L carry the
//     fused lane-ctl tau of block L+1.
// ---------------------------------------------------------------------------
template<int L, int W>
__device__ __forceinline__ void standalone_taus(float2 sr[16], float2 si[16], int lane) {
    if constexpr (W <= 9 - L) {
        cnot_gate<L, 9 - W, 9 - W - L>(sr, si, lane);
        standalone_taus<L, W + 1>(sr, si, lane);
    }
}
template<int L, int W>
__device__ __forceinline__ void fused_stages(float2 sr[16], float2 si[16], int lane,
                                             const float2* __restrict__ ry) {
    if constexpr (W <= 9) {
        constexpr int Bc = 9 - W;          // local control bit (0..L-1)
        constexpr int B5 = 14 - W - L;     // logical lane-space target bit (0..4)
        fused_cnot_ry<L, Bc, B5>(sr, si, lane, __ldg(ry + (W + L - 10)));
        fused_stages<L, W + 1>(sr, si, lane, ry);
    }
}
template<int L, int Q>
__device__ __forceinline__ void remaining_gates(float2 sr[16], float2 si[16], int lane,
                                                const float2* __restrict__ ry) {
    if constexpr (Q <= 9) {
        if constexpr (Q <= 4) {
            ry_lane_gate<L, 4 - Q>(sr, si, lane, __ldg(ry + Q));
        } else {
            constexpr int B = 9 - Q;
            if constexpr (L <= 4 && B >= 4 - L)
                ry_local_gate_fused<L, B>(sr, si, lane, __ldg(ry + Q));
            else
                ry_local_gate<B>(sr, si, __ldg(ry + Q));
        }
        remaining_gates<L, Q + 1>(sr, si, lane, ry);
    }
}
template<int L>
__device__ __forceinline__ void fused_layer(float2 sr[16], float2 si[16], int lane) {
    apply_diag(sr, si, lane, g_E[L - 1]);
    standalone_taus<L, 5>(sr, si, lane);       // local/local only
    fused_stages<L, 10 - L>(sr, si, lane, g_ry[L]);
    remaining_gates<L, L>(sr, si, lane, g_ry[L]);
}

// ---------------------------------------------------------------------------
// Main kernel: one warp per sample; 256 thr, 2 CTAs/SM (128 regs, no spill).
// ---------------------------------------------------------------------------
__global__ void __launch_bounds__(256, 2) qcnn_kernel(
    const float* __restrict__ x,
    const float* __restrict__ fc_b,
    float* __restrict__ out)
{
    const int warp = (blockIdx.x * blockDim.x + threadIdx.x) >> 5;
    const int lane = threadIdx.x & 31;
    if (warp >= BATCH) return;

    // --- initial product state magnitudes (Λ = identity here) ---------------
    const float* xb = x + warp * NQ;
    float cq[NQ], sq[NQ];
    #pragma unroll
    for (int q = 0; q < NQ; ++q) {
        float h = 0.5f * __ldg(xb + q);
        sincosf(h, &sq[q], &cq[q]);
    }
    float A = 1.f;
    #pragma unroll
    for (int q = 0; q < 5; ++q)
        A *= ((lane >> (4 - q)) & 1) ? sq[q] : cq[q];

    float m[16];
    m[0] = A;
    #pragma unroll
    for (int t = 0; t < 4; ++t) {
        const int q = 8 - t;
        const int sz = 1 << t;
        #pragma unroll
        for (int k = sz - 1; k >= 0; --k) {
            float v = m[k];
            m[k + sz] = v * sq[q];
            m[k]      = v * cq[q];
        }
    }
    float2 sr[16], si[16];
    #pragma unroll
    for (int k = 0; k < 16; ++k) {
        float4 t = __ldg(&g_T0[k * 32 + lane]);
        float2 mag2 = make_float2(m[k] * cq[9], m[k] * sq[9]);
        sr[k] = fmul2_(mag2, make_float2(t.x, t.z));
        si[k] = fmul2_(mag2, make_float2(t.y, t.w));
    }

    // --- circuit -------------------------------------------------------------
    remaining_gates<0, 0>(sr, si, lane, g_ry[0]);   // Y_0 (+ fused tau of block 1)
    fused_layer<1>(sr, si, lane);
    fused_layer<2>(sr, si, lane);
    fused_layer<3>(sr, si, lane);
    fused_layer<4>(sr, si, lane);
    fused_layer<5>(sr, si, lane);
    // P_5 (r=6) and Λ_5 fully virtualized into the epilogue weight table.

    // --- epilogue: out = sum_m w_m |psi_m|^2, w from precomputed table -------
    float2 acc2 = make_float2(0.f, 0.f);
    #pragma unroll
    for (int k = 0; k < 16; ++k) {
        float2 w2 = __ldg(&g_W[k * 32 + lane]);
        float2 p2 = ffma2_(si[k], si[k], fmul2_(sr[k], sr[k]));
        acc2 = ffma2_(w2, p2, acc2);
    }
    float acc = acc2.x + acc2.y;
    #pragma unroll
    for (int off = 16; off; off >>= 1)
        acc += __shfl_xor_sync(0xffffffffu, acc, off);

    if (lane == 0) out[warp] = acc + __ldg(fc_b);
}

// ---------------------------------------------------------------------------
extern "C" void kernel_launch(void* const* d_in, const int* in_sizes, int n_in,
                              void* d_out, int out_size) {
    const float* x    = (const float*)d_in[0];   // (16384, 10)
    const float* ql   = (const float*)d_in[1];   // (6, 10, 3)
    const float* fcw  = (const float*)d_in[2];   // (1, 10)
    const float* fcb  = (const float*)d_in[3];   // (1,)
    float* out = (float*)d_out;                  // (16384, 1)

    table_kernel<<<7, 512>>>(ql, fcw);
    qcnn_kernel<<<BATCH / 8, 256>>>(x, fcb, out);
}

// round 13
// speedup vs baseline: 1.8018x; 1.1101x over previous
#include <cuda_runtime.h>

#define NQ      10
#define DIM     1024
#define NLAYERS 6
#define BATCH   16384

typedef unsigned long long ull;

// Precomputed tables (sample-independent):
//  g_ry[l][q] = (cos θ/2, sin θ/2)
//  g_T0[idx]  = init phases, layout (c0, c1, s0, s1)  [c-pack | s-pack]
//  g_E[l-1][idx] = fused diagonal, same (c0,c1,s0,s1) layout
//                  (Λ-baked AND conjugated past the moved lane-ctl taus)
//  g_W[idx]   = epilogue weights (S6^{-1} and Λ_5 baked), (w0,w1)
// idx = k*32 + lane (physical); pair covers local pack k, components 0/1.
__device__ float2 g_ry[NLAYERS][NQ];
__device__ __align__(16) float4 g_T0[512];
__device__ __align__(16) float4 g_E[5][512];
__device__ __align__(8)  float2 g_W[512];

// ---------------------------------------------------------------------------
// GF(2) algebra.
// ---------------------------------------------------------------------------
__host__ __device__ constexpr int s6inv_map(int m) {
    for (int w = 0; w < 10; ++w) {
        int cb = 9 - w, tb = 9 - ((w + 6) % 10);
        m ^= ((m >> cb) & 1) << tb;
    }
    return m;
}
__host__ __device__ constexpr int lam_after(int L, int v) {
    for (int l = 1; l <= L; ++l)
        for (int w = 0; w + l <= 4; ++w) {
            int c = 4 - w, t = 4 - w - l;
            v ^= ((v >> c) & 1) << t;
        }
    return v;
}
__host__ __device__ constexpr int inv_mask(int L, int b) {
    for (int v = 1; v < 32; ++v)
        if (lam_after(L, v) == (1 << b)) return v;
    return 0;
}
__host__ __device__ constexpr int row_mask(int L, int b) {
    int r = 0;
    for (int j = 0; j < 5; ++j)
        r |= ((lam_after(L, 1 << j) >> b) & 1) << j;
    return r;
}

// ---------------------------------------------------------------------------
// Packed f32x2 helpers on 64-bit values ("l" constraints keep PTX in .b64 —
// ptxas allocates aligned pairs once; no pack/unpack movs inside chains).
// ---------------------------------------------------------------------------
__device__ __forceinline__ ull ffma2u(ull a, ull b, ull c) {
    ull d;
    asm("fma.rn.f32x2 %0,%1,%2,%3;" : "=l"(d) : "l"(a), "l"(b), "l"(c));
    return d;
}
__device__ __forceinline__ ull fmul2u(ull a, ull b) {
    ull d;
    asm("mul.rn.f32x2 %0,%1,%2;" : "=l"(d) : "l"(a), "l"(b));
    return d;
}
__device__ __forceinline__ ull fsub2u(ull a, ull b) {
    ull d;
    asm("sub.rn.f32x2 %0,%1,%2;" : "=l"(d) : "l"(a), "l"(b));
    return d;
}
__device__ __forceinline__ ull pack2(float x, float y) {
    ull d;
    asm("mov.b64 %0,{%1,%2};" : "=l"(d) : "f"(x), "f"(y));
    return d;
}
__device__ __forceinline__ void unpack2(ull v, float& x, float& y) {
    asm("mov.b64 {%0,%1},%2;" : "=f"(x), "=f"(y) : "l"(v));
}
__device__ __forceinline__ ull bc2u(float v) { return pack2(v, v); }
__device__ __forceinline__ ull swap2(ull v) {
    float x, y; unpack2(v, x, y); return pack2(y, x);
}
__device__ __forceinline__ ull shflx2(ull v, unsigned msk) {
    float x, y; unpack2(v, x, y);
    x = __shfl_xor_sync(0xffffffffu, x, msk);
    y = __shfl_xor_sync(0xffffffffu, y, msk);
    return pack2(x, y);
}

// ---------------------------------------------------------------------------
// Pre-kernel: one job per block. Job 0: g_ry + T0; jobs 1..5: E_l; job 6: W.
// ---------------------------------------------------------------------------
__device__ __forceinline__ float sum_signed(int n, const float* ql, int l, int off) {
    float a = 0.f;
    #pragma unroll
    for (int q = 0; q < NQ; ++q) {
        float v = ql[(l * NQ + q) * 3 + off];
        a += ((n >> (9 - q)) & 1) ? v : -v;
    }
    return 0.5f * a;
}

__global__ void table_kernel(const float* __restrict__ ql,
                             const float* __restrict__ fcw) {
    const int idx = threadIdx.x;      // 0..511
    const int job = blockIdx.x;       // 0..6
    const int k = idx >> 5, lane = idx & 31;

    if (job == 0) {
        if (idx < NLAYERS * NQ) {
            int l = idx / NQ, q = idx % NQ;
            float s, c; sincosf(0.5f * ql[(l * NQ + q) * 3 + 1], &s, &c);
            g_ry[l][q] = make_float2(c, s);
        }
        // T0 (Λ = identity): (-i)^popc(n) * Dphi_0[n]; layout (c0,c1,s0,s1)
        float cs[2], sn[2];
        #pragma unroll
        for (int comp = 0; comp < 2; ++comp) {
            int n = (lane << 5) | (k << 1) | comp;
            float ang = -1.57079632679f * __popc(n) + sum_signed(n, ql, 0, 0);
            sincosf(ang, &sn[comp], &cs[comp]);
        }
        g_T0[idx] = make_float4(cs[0], cs[1], sn[0], sn[1]);
    } else if (job <= 5) {
        // E_l, Λ_{l-1}-baked, conjugated past the moved lane-ctl taus of
        // block l: E'[p,j] = E[p, j ^ f(p)]. Layout (c0,c1,s0,s1).
        const int l = job;
        int llog = lam_after(l - 1, lane);
        int f = 0;
        for (int w = 5 - l; w <= 4; ++w)
            if (__popc(lane & row_mask(l, 4 - w)) & 1) f ^= 1 << (9 - w - l);
        float cs[2], sn[2];
        #pragma unroll
        for (int comp = 0; comp < 2; ++comp) {
            int n = ((llog << 5) | (k << 1) | comp) ^ f;
            float angw = sum_signed(n, ql, l - 1, 2);
            int p = n;             // sigma^{-1}: apply tau_0 .. tau_9 in order
            #pragma unroll
            for (int w = 0; w < NQ; ++w) {
                int cbit = 9 - w;
                int tbit = 9 - ((w + l) % NQ);
                p ^= ((p >> cbit) & 1) << tbit;
            }
            float angp = sum_signed(p, ql, l, 0);
            sincosf(angw + angp, &sn[comp], &cs[comp]);
        }
        g_E[l - 1][idx] = make_float4(cs[0], cs[1], sn[0], sn[1]);
    } else {
        // Epilogue weights with Λ_5 and S6^{-1} baked.
        int llog = lam_after(5, lane);
        float wv[2];
        #pragma unroll
        for (int comp = 0; comp < 2; ++comp) {
            int n = (llog << 5) | (k << 1) | comp;
            int p = s6inv_map(n);
            float a = 0.f;
            #pragma unroll
            for (int q = 0; q < NQ; ++q) {
                float v = fcw[q];
                a += ((p >> (9 - q)) & 1) ? -v : v;
            }
            wv[comp] = a;
        }
        g_W[idx] = make_float2(wv[0], wv[1]);
    }
}

// ---------------------------------------------------------------------------
// State layout: logical amplitude n: bits 9..5 lane (via Λ), 4..1 pack k,
// 0 comp (low/high float of the ull). Qubit q acts on logical bit 9-q.
// ---------------------------------------------------------------------------

// RY gate on logical lane-space bit B5 (layer-block context L for Λ).
template<int L, int B5>
__device__ __forceinline__ void ry_lane_gate(ull sr[16], ull si[16], int lane,
                                             float2 g) {
    constexpr unsigned msk = (unsigned)inv_mask(L, B5);
    constexpr int row = row_mask(L, B5);
    const bool hi = __popc(lane & row) & 1;
    const ull c2 = bc2u(g.x);
    const ull s2 = bc2u(hi ? g.y : -g.y);
    #pragma unroll
    for (int k = 0; k < 16; ++k) {
        ull qr = shflx2(sr[k], msk);
        ull qi = shflx2(si[k], msk);
        sr[k] = ffma2u(s2, qr, fmul2u(c2, sr[k]));
        si[k] = ffma2u(s2, qi, fmul2u(c2, si[k]));
    }
}

// Plain RY gate on local bit B (1..4 = pack bit B-1; 0 = comp bit).
template<int B>
__device__ __forceinline__ void ry_local_gate(ull sr[16], ull si[16], float2 g) {
    if constexpr (B >= 1) {
        constexpr int pb = B - 1;
        const ull cl2 = bc2u(g.x), sl2 = bc2u(g.y), nsl2 = bc2u(-g.y);
        #pragma unroll
        for (int t = 0; t < 8; ++t) {
            const int k  = ((t >> pb) << (pb + 1)) | (t & ((1 << pb) - 1));
            const int k2 = k | (1 << pb);
            ull Ar = sr[k], Ai = si[k], Br = sr[k2], Bi = si[k2];
            sr[k]  = ffma2u(nsl2, Br, fmul2u(cl2, Ar));
            si[k]  = ffma2u(nsl2, Bi, fmul2u(cl2, Ai));
            sr[k2] = ffma2u(cl2, Br, fmul2u(sl2, Ar));
            si[k2] = ffma2u(cl2, Bi, fmul2u(sl2, Ai));
        }
    } else {
        const ull c2  = bc2u(g.x);
        const ull sp2 = pack2(-g.y, g.y);
        #pragma unroll
        for (int k = 0; k < 16; ++k) {
            ull wr = swap2(sr[k]), wi = swap2(si[k]);
            sr[k] = ffma2u(sp2, wr, fmul2u(c2, sr[k]));
            si[k] = ffma2u(sp2, wi, fmul2u(c2, si[k]));
        }
    }
}

// RY local gate on bit B, fused with a FOLLOWING lane-ctl CNOT from block J+1.
template<int J, int B>
__device__ __forceinline__ void ry_local_gate_fused(ull sr[16], ull si[16],
                                                    int lane, float2 g) {
    constexpr int row = row_mask(J + 1, B + J - 4);
    const bool ctl = __popc(lane & row) & 1;
    const float cl = g.x, sl = g.y;
    if constexpr (B >= 1) {
        constexpr int pb = B - 1;
        const ull a1 = bc2u(ctl ? sl :  cl);
        const ull b1 = bc2u(ctl ? cl : -sl);
        const ull a2 = bc2u(ctl ? cl :  sl);
        const ull b2 = bc2u(ctl ? -sl : cl);
        #pragma unroll
        for (int t = 0; t < 8; ++t) {
            const int k  = ((t >> pb) << (pb + 1)) | (t & ((1 << pb) - 1));
            const int k2 = k | (1 << pb);
            ull Ar = sr[k], Ai = si[k], Br = sr[k2], Bi = si[k2];
            sr[k]  = ffma2u(b1, Br, fmul2u(a1, Ar));
            si[k]  = ffma2u(b1, Bi, fmul2u(a1, Ai));
            sr[k2] = ffma2u(b2, Br, fmul2u(a2, Ar));
            si[k2] = ffma2u(b2, Bi, fmul2u(a2, Ai));
        }
    } else {
        const ull c2  = pack2(ctl ? sl :  cl, ctl ? -sl : cl);
        const ull sp2 = pack2(ctl ? cl : -sl, ctl ?  cl : sl);
        #pragma unroll
        for (int k = 0; k < 16; ++k) {
            ull wr = swap2(sr[k]), wi = swap2(si[k]);
            sr[k] = ffma2u(sp2, wr, fmul2u(c2, sr[k]));
            si[k] = ffma2u(sp2, wi, fmul2u(c2, si[k]));
        }
    }
}

// Fused stage: CNOT(local control bit Bc -> logical lane bit B5) + RY(target).
template<int L, int Bc, int B5>
__device__ __forceinline__ void fused_cnot_ry(ull sr[16], ull si[16], int lane,
                                              float2 g) {
    constexpr unsigned msk = (unsigned)inv_mask(L, B5);
    constexpr int row = row_mask(L, B5);
    const bool hi = __popc(lane & row) & 1;
    const float sg = hi ? g.y : -g.y;
    if constexpr (Bc == 0) {
        const ull A = pack2(g.x, sg);
        const ull B = pack2(sg, g.x);
        #pragma unroll
        for (int k = 0; k < 16; ++k) {
            ull qr = shflx2(sr[k], msk);
            ull qi = shflx2(si[k], msk);
            sr[k] = ffma2u(B, qr, fmul2u(A, sr[k]));
            si[k] = ffma2u(B, qi, fmul2u(A, si[k]));
        }
    } else {
        const ull c2 = bc2u(g.x), s2 = bc2u(sg);
        #pragma unroll
        for (int k = 0; k < 16; ++k) {
            ull qr = shflx2(sr[k], msk);
            ull qi = shflx2(si[k], msk);
            const bool ctl = (k >> (Bc - 1)) & 1;       // compile-time after unroll
            const ull A = ctl ? s2 : c2;
            const ull B = ctl ? c2 : s2;
            sr[k] = ffma2u(B, qr, fmul2u(A, sr[k]));
            si[k] = ffma2u(B, qi, fmul2u(A, si[k]));
        }
    }
}

// ---------------------------------------------------------------------------
// Standalone CNOT: local control bit BC (>=1), local/comp target BT.
// ---------------------------------------------------------------------------
template<int L, int BC, int BT>
__device__ __forceinline__ void cnot_gate(ull sr[16], ull si[16], int lane) {
    if constexpr (BC >= 1 && BT >= 1) {
        constexpr int pbc = BC - 1, pbt = BT - 1;
        #pragma unroll
        for (int k = 0; k < 16; ++k) {
            if (((k >> pbc) & 1) && !((k >> pbt) & 1)) {
                const int k2 = k | (1 << pbt);
                ull t;
                t = sr[k]; sr[k] = sr[k2]; sr[k2] = t;
                t = si[k]; si[k] = si[k2]; si[k2] = t;
            }
        }
    } else {   // BC >= 1, BT == 0
        constexpr int pb = BC - 1;
        #pragma unroll
        for (int k = 0; k < 16; ++k) {
            if ((k >> pb) & 1) {
                sr[k] = swap2(sr[k]);
                si[k] = swap2(si[k]);
            }
        }
    }
}

// fused diagonal: per pack complex multiply by table phase.
// 16 INDEPENDENT loads — ptxas front-batches them (MLP ~16). Do NOT chain
// them through one register ("prefetch"): that serializes the loads (R11).
// Table layout (c0,c1,s0,s1): .x of the ulonglong2 IS the c-pack, .y the s-pack.
__device__ __forceinline__ void apply_diag(ull sr[16], ull si[16], int lane,
                                           const float4* __restrict__ tbl) {
    const ulonglong2* t2 = reinterpret_cast<const ulonglong2*>(tbl);
    #pragma unroll
    for (int k = 0; k < 16; ++k) {
        ulonglong2 t = __ldg(t2 + k * 32 + lane);
        ull c = t.x, s = t.y;
        ull r = sr[k], i = si[k];
        sr[k] = fsub2u(fmul2u(c, r), fmul2u(s, i));
        si[k] = ffma2u(c, i, fmul2u(s, r));
    }
}

// ---------------------------------------------------------------------------
// Block L (shift r = L):
//  1. (moved lane-ctl taus of this block already executed inside layer L-1)
//  2. diag E_L (table conjugated accordingly)
//  3. lane/lane taus: DEFERRED into Λ (free)
//  4. standalone local/local taus w = 5..9-L (register renaming, ~free)
//  5. fused stages w = 10-L..9: CNOT(local ctl -> lane tgt) + RY
//  6. remaining RY gates q = L..9; local gates on bits B >= 4-L carry the
//     fused lane-ctl tau of block L+1.
// ---------------------------------------------------------------------------
template<int L, int W>
__device__ __forceinline__ void standalone_taus(ull sr[16], ull si[16], int lane) {
    if constexpr (W <= 9 - L) {
        cnot_gate<L, 9 - W, 9 - W - L>(sr, si, lane);
        standalone_taus<L, W + 1>(sr, si, lane);
    }
}
template<int L, int W>
__device__ __forceinline__ void fused_stages(ull sr[16], ull si[16], int lane,
                                             const float2* __restrict__ ry) {
    if constexpr (W <= 9) {
        constexpr int Bc = 9 - W;          // local control bit (0..L-1)
        constexpr int B5 = 14 - W - L;     // logical lane-space target bit (0..4)
        fused_cnot_ry<L, Bc, B5>(sr, si, lane, __ldg(ry + (W + L - 10)));
        fused_stages<L, W + 1>(sr, si, lane, ry);
    }
}
template<int L, int Q>
__device__ __forceinline__ void remaining_gates(ull sr[16], ull si[16], int lane,
                                                const float2* __restrict__ ry) {
    if constexpr (Q <= 9) {
        if constexpr (Q <= 4) {
            ry_lane_gate<L, 4 - Q>(sr, si, lane, __ldg(ry + Q));
        } else {
            constexpr int B = 9 - Q;
            if constexpr (L <= 4 && B >= 4 - L)
                ry_local_gate_fused<L, B>(sr, si, lane, __ldg(ry + Q));
            else
                ry_local_gate<B>(sr, si, __ldg(ry + Q));
        }
        remaining_gates<L, Q + 1>(sr, si, lane, ry);
    }
}
template<int L>
__device__ __forceinline__ void fused_layer(ull sr[16], ull si[16], int lane) {
    apply_diag(sr, si, lane, g_E[L - 1]);
    standalone_taus<L, 5>(sr, si, lane);       // local/local only
    fused_stages<L, 10 - L>(sr, si, lane, g_ry[L]);
    remaining_gates<L, L>(sr, si, lane, g_ry[L]);
}

// ---------------------------------------------------------------------------
// Main kernel: one warp per sample; 256 thr, 2 CTAs/SM (~126 regs, no spill).
// ---------------------------------------------------------------------------
__global__ void __launch_bounds__(256, 2) qcnn_kernel(
    const float* __restrict__ x,
    const float* __restrict__ fc_b,
    float* __restrict__ out)
{
    const int warp = (blockIdx.x * blockDim.x + threadIdx.x) >> 5;
    const int lane = threadIdx.x & 31;
    if (warp >= BATCH) return;

    // --- initial product state magnitudes (Λ = identity here) ---------------
    const float* xb = x + warp * NQ;
    float cq[NQ], sq[NQ];
    #pragma unroll
    for (int q = 0; q < NQ; ++q) {
        float h = 0.5f * __ldg(xb + q);
        __sincosf(h, &sq[q], &cq[q]);
    }
    float A = 1.f;
    #pragma unroll
    for (int q = 0; q < 5; ++q)
        A *= ((lane >> (4 - q)) & 1) ? sq[q] : cq[q];

    float m[16];
    m[0] = A;
    #pragma unroll
    for (int t = 0; t < 4; ++t) {
        const int q = 8 - t;
        const int sz = 1 << t;
        #pragma unroll
        for (int k = sz - 1; k >= 0; --k) {
            float v = m[k];
            m[k + sz] = v * sq[q];
            m[k]      = v * cq[q];
        }
    }
    ull sr[16], si[16];
    {
        const ulonglong2* t2 = reinterpret_cast<const ulonglong2*>(g_T0);
        #pragma unroll
        for (int k = 0; k < 16; ++k) {
            ulonglong2 t = __ldg(t2 + k * 32 + lane);
            ull mag2 = pack2(m[k] * cq[9], m[k] * sq[9]);
            sr[k] = fmul2u(mag2, t.x);
            si[k] = fmul2u(mag2, t.y);
        }
    }

    // --- circuit -------------------------------------------------------------
    remaining_gates<0, 0>(sr, si, lane, g_ry[0]);   // Y_0 (+ fused tau of block 1)
    fused_layer<1>(sr, si, lane);
    fused_layer<2>(sr, si, lane);
    fused_layer<3>(sr, si, lane);
    fused_layer<4>(sr, si, lane);
    fused_layer<5>(sr, si, lane);
    // P_5 (r=6) and Λ_5 fully virtualized into the epilogue weight table.

    // --- epilogue: out = sum_m w_m |psi_m|^2, w from precomputed table -------
    const ull* wtab = reinterpret_cast<const ull*>(g_W);
    ull acc2 = pack2(0.f, 0.f);
    #pragma unroll
    for (int k = 0; k < 16; ++k) {
        ull w2 = __ldg(wtab + k * 32 + lane);
        ull p2 = ffma2u(si[k], si[k], fmul2u(sr[k], sr[k]));
        acc2 = ffma2u(w2, p2, acc2);
    }
    float ax, ay; unpack2(acc2, ax, ay);
    float acc = ax + ay;
    #pragma unroll
    for (int off = 16; off; off >>= 1)
        acc += __shfl_xor_sync(0xffffffffu, acc, off);

    if (lane == 0) out[warp] = acc + __ldg(fc_b);
}

// ---------------------------------------------------------------------------
extern "C" void kernel_launch(void* const* d_in, const int* in_sizes, int n_in,
                              void* d_out, int out_size) {
    const float* x    = (const float*)d_in[0];   // (16384, 10)
    const float* ql   = (const float*)d_in[1];   // (6, 10, 3)
    const float* fcw  = (const float*)d_in[2];   // (1, 10)
    const float* fcb  = (const float*)d_in[3];   // (1,)
    float* out = (float*)d_out;                  // (16384, 1)

    table_kernel<<<7, 512>>>(ql, fcw);
    qcnn_kernel<<<BATCH / 8, 256>>>(x, fcb, out);
}

// round 14
// speedup vs baseline: 1.9637x; 1.0899x over previous
#include <cuda_runtime.h>

#define NQ      10
#define DIM     1024
#define NLAYERS 6
#define BATCH   16384

typedef unsigned long long ull;

// Precomputed tables (sample-independent):
//  g_ry[l][q] = (tan θ/2, cos θ/2)   — gates use .x = t; scale uses cos
//  g_T0[idx]  = init phases, layout (c0, c1, s0, s1)  [c-pack | s-pack]
//  g_E[l-1][idx] = fused diagonal, same layout (Λ-baked + tau-conjugated)
//  g_W[idx]   = epilogue weights (S6^{-1}, Λ_5, and (Πcos)² scale baked)
// idx = k*32 + lane (physical); pair covers local pack k, components 0/1.
// RY gates run in TANGENT form (each gate divided by its cos); the global
// factor (Π cos)² is folded into g_W.
__device__ float2 g_ry[NLAYERS][NQ];
__device__ __align__(16) float4 g_T0[512];
__device__ __align__(16) float4 g_E[5][512];
__device__ __align__(8)  float2 g_W[512];

// ---------------------------------------------------------------------------
// GF(2) algebra.
// ---------------------------------------------------------------------------
__host__ __device__ constexpr int s6inv_map(int m) {
    for (int w = 0; w < 10; ++w) {
        int cb = 9 - w, tb = 9 - ((w + 6) % 10);
        m ^= ((m >> cb) & 1) << tb;
    }
    return m;
}
__host__ __device__ constexpr int lam_after(int L, int v) {
    for (int l = 1; l <= L; ++l)
        for (int w = 0; w + l <= 4; ++w) {
            int c = 4 - w, t = 4 - w - l;
            v ^= ((v >> c) & 1) << t;
        }
    return v;
}
__host__ __device__ constexpr int inv_mask(int L, int b) {
    for (int v = 1; v < 32; ++v)
        if (lam_after(L, v) == (1 << b)) return v;
    return 0;
}
__host__ __device__ constexpr int row_mask(int L, int b) {
    int r = 0;
    for (int j = 0; j < 5; ++j)
        r |= ((lam_after(L, 1 << j) >> b) & 1) << j;
    return r;
}

// ---------------------------------------------------------------------------
// Packed f32x2 helpers on 64-bit values ("l" constraints keep PTX in .b64).
// ---------------------------------------------------------------------------
__device__ __forceinline__ ull ffma2u(ull a, ull b, ull c) {
    ull d;
    asm("fma.rn.f32x2 %0,%1,%2,%3;" : "=l"(d) : "l"(a), "l"(b), "l"(c));
    return d;
}
__device__ __forceinline__ ull fmul2u(ull a, ull b) {
    ull d;
    asm("mul.rn.f32x2 %0,%1,%2;" : "=l"(d) : "l"(a), "l"(b));
    return d;
}
__device__ __forceinline__ ull fsub2u(ull a, ull b) {
    ull d;
    asm("sub.rn.f32x2 %0,%1,%2;" : "=l"(d) : "l"(a), "l"(b));
    return d;
}
__device__ __forceinline__ ull pack2(float x, float y) {
    ull d;
    asm("mov.b64 %0,{%1,%2};" : "=l"(d) : "f"(x), "f"(y));
    return d;
}
__device__ __forceinline__ void unpack2(ull v, float& x, float& y) {
    asm("mov.b64 {%0,%1},%2;" : "=f"(x), "=f"(y) : "l"(v));
}
__device__ __forceinline__ ull bc2u(float v) { return pack2(v, v); }
__device__ __forceinline__ ull swap2(ull v) {
    float x, y; unpack2(v, x, y); return pack2(y, x);
}
__device__ __forceinline__ ull shflx2(ull v, unsigned msk) {
    float x, y; unpack2(v, x, y);
    x = __shfl_xor_sync(0xffffffffu, x, msk);
    y = __shfl_xor_sync(0xffffffffu, y, msk);
    return pack2(x, y);
}

// ---------------------------------------------------------------------------
// Pre-kernel: one job per block. Job 0: g_ry + T0; jobs 1..5: E_l; job 6: W.
// ---------------------------------------------------------------------------
__device__ __forceinline__ float sum_signed(int n, const float* ql, int l, int off) {
    float a = 0.f;
    #pragma unroll
    for (int q = 0; q < NQ; ++q) {
        float v = ql[(l * NQ + q) * 3 + off];
        a += ((n >> (9 - q)) & 1) ? v : -v;
    }
    return 0.5f * a;
}

__global__ void table_kernel(const float* __restrict__ ql,
                             const float* __restrict__ fcw) {
    const int idx = threadIdx.x;      // 0..511
    const int job = blockIdx.x;       // 0..6
    const int k = idx >> 5, lane = idx & 31;

    if (job == 0) {
        if (idx < NLAYERS * NQ) {
            int l = idx / NQ, q = idx % NQ;
            float s, c; sincosf(0.5f * ql[(l * NQ + q) * 3 + 1], &s, &c);
            g_ry[l][q] = make_float2(s / c, c);   // (tan, cos)
        }
        // T0 (Λ = identity): (-i)^popc(n) * Dphi_0[n]; layout (c0,c1,s0,s1)
        float cs[2], sn[2];
        #pragma unroll
        for (int comp = 0; comp < 2; ++comp) {
            int n = (lane << 5) | (k << 1) | comp;
            float ang = -1.57079632679f * __popc(n) + sum_signed(n, ql, 0, 0);
            sincosf(ang, &sn[comp], &cs[comp]);
        }
        g_T0[idx] = make_float4(cs[0], cs[1], sn[0], sn[1]);
    } else if (job <= 5) {
        // E_l, Λ_{l-1}-baked, conjugated past the moved lane-ctl taus of
        // block l: E'[p,j] = E[p, j ^ f(p)]. Layout (c0,c1,s0,s1).
        const int l = job;
        int llog = lam_after(l - 1, lane);
        int f = 0;
        for (int w = 5 - l; w <= 4; ++w)
            if (__popc(lane & row_mask(l, 4 - w)) & 1) f ^= 1 << (9 - w - l);
        float cs[2], sn[2];
        #pragma unroll
        for (int comp = 0; comp < 2; ++comp) {
            int n = ((llog << 5) | (k << 1) | comp) ^ f;
            float angw = sum_signed(n, ql, l - 1, 2);
            int p = n;             // sigma^{-1}: apply tau_0 .. tau_9 in order
            #pragma unroll
            for (int w = 0; w < NQ; ++w) {
                int cbit = 9 - w;
                int tbit = 9 - ((w + l) % NQ);
                p ^= ((p >> cbit) & 1) << tbit;
            }
            float angp = sum_signed(p, ql, l, 0);
            sincosf(angw + angp, &sn[comp], &cs[comp]);
        }
        g_E[l - 1][idx] = make_float4(cs[0], cs[1], sn[0], sn[1]);
    } else {
        // Epilogue weights with Λ_5, S6^{-1}, and (Π cos)^2 scale baked.
        float sc = 1.f;
        #pragma unroll 1
        for (int i = 0; i < NLAYERS * NQ; ++i)
            sc *= cosf(0.5f * ql[i * 3 + 1]);
        const float sc2 = sc * sc;
        int llog = lam_after(5, lane);
        float wv[2];
        #pragma unroll
        for (int comp = 0; comp < 2; ++comp) {
            int n = (llog << 5) | (k << 1) | comp;
            int p = s6inv_map(n);
            float a = 0.f;
            #pragma unroll
            for (int q = 0; q < NQ; ++q) {
                float v = fcw[q];
                a += ((p >> (9 - q)) & 1) ? -v : v;
            }
            wv[comp] = a * sc2;
        }
        g_W[idx] = make_float2(wv[0], wv[1]);
    }
}

// ---------------------------------------------------------------------------
// State layout: logical amplitude n: bits 9..5 lane (via Λ), 4..1 pack k,
// 0 comp (low/high float of the ull). Qubit q acts on logical bit 9-q.
// All RY gates in tangent form: out = (A - tB, tA + B); global cos product
// deferred into g_W.
// ---------------------------------------------------------------------------

// RY gate on logical lane-space bit B5 (layer-block context L for Λ).
template<int L, int B5>
__device__ __forceinline__ void ry_lane_gate(ull sr[16], ull si[16], int lane,
                                             float2 g) {
    constexpr unsigned msk = (unsigned)inv_mask(L, B5);
    constexpr int row = row_mask(L, B5);
    const bool hi = __popc(lane & row) & 1;
    const ull st2 = bc2u(hi ? g.x : -g.x);       // ± tan
    #pragma unroll
    for (int k = 0; k < 16; ++k) {
        ull qr = shflx2(sr[k], msk);
        ull qi = shflx2(si[k], msk);
        sr[k] = ffma2u(st2, qr, sr[k]);          // v + (±t) q
        si[k] = ffma2u(st2, qi, si[k]);
    }
}

// Plain RY gate on local bit B (1..4 = pack bit B-1; 0 = comp bit).
template<int B>
__device__ __forceinline__ void ry_local_gate(ull sr[16], ull si[16], float2 g) {
    if constexpr (B >= 1) {
        constexpr int pb = B - 1;
        const ull t2 = bc2u(g.x), nt2 = bc2u(-g.x);
        #pragma unroll
        for (int t = 0; t < 8; ++t) {
            const int k  = ((t >> pb) << (pb + 1)) | (t & ((1 << pb) - 1));
            const int k2 = k | (1 << pb);
            ull Ar = sr[k], Ai = si[k], Br = sr[k2], Bi = si[k2];
            sr[k]  = ffma2u(nt2, Br, Ar);        // A - tB
            si[k]  = ffma2u(nt2, Bi, Ai);
            sr[k2] = ffma2u(t2, Ar, Br);         // tA + B
            si[k2] = ffma2u(t2, Ai, Bi);
        }
    } else {
        const ull tp2 = pack2(-g.x, g.x);
        #pragma unroll
        for (int k = 0; k < 16; ++k) {
            sr[k] = ffma2u(tp2, swap2(sr[k]), sr[k]);
            si[k] = ffma2u(tp2, swap2(si[k]), si[k]);
        }
    }
}

// RY local gate on bit B, fused with a FOLLOWING lane-ctl CNOT from block J+1.
// Compute both tangent-form rows; runtime ctl swaps which output gets which.
template<int J, int B>
__device__ __forceinline__ void ry_local_gate_fused(ull sr[16], ull si[16],
                                                    int lane, float2 g) {
    constexpr int row = row_mask(J + 1, B + J - 4);
    const bool ctl = __popc(lane & row) & 1;
    if constexpr (B >= 1) {
        constexpr int pb = B - 1;
        const ull t2 = bc2u(g.x), nt2 = bc2u(-g.x);
        #pragma unroll
        for (int t = 0; t < 8; ++t) {
            const int k  = ((t >> pb) << (pb + 1)) | (t & ((1 << pb) - 1));
            const int k2 = k | (1 << pb);
            ull Ar = sr[k], Ai = si[k], Br = sr[k2], Bi = si[k2];
            ull ur = ffma2u(nt2, Br, Ar), wr = ffma2u(t2, Ar, Br);
            ull ui = ffma2u(nt2, Bi, Ai), wi = ffma2u(t2, Ai, Bi);
            sr[k]  = ctl ? wr : ur;   sr[k2] = ctl ? ur : wr;
            si[k]  = ctl ? wi : ui;   si[k2] = ctl ? ui : wi;
        }
    } else {
        // u = v + (-t,t).*swap(v); ctl output = swap(u)  (identity verified)
        const ull tp2 = pack2(-g.x, g.x);
        #pragma unroll
        for (int k = 0; k < 16; ++k) {
            ull ur = ffma2u(tp2, swap2(sr[k]), sr[k]);
            ull ui = ffma2u(tp2, swap2(si[k]), si[k]);
            sr[k] = ctl ? swap2(ur) : ur;
            si[k] = ctl ? swap2(ui) : ui;
        }
    }
}

// Fused stage: CNOT(local control bit Bc -> logical lane bit B5) + RY(target).
template<int L, int Bc, int B5>
__device__ __forceinline__ void fused_cnot_ry(ull sr[16], ull si[16], int lane,
                                              float2 g) {
    constexpr unsigned msk = (unsigned)inv_mask(L, B5);
    constexpr int row = row_mask(L, B5);
    const bool hi = __popc(lane & row) & 1;
    const float tg = hi ? g.x : -g.x;
    if constexpr (Bc == 0) {
        // A' = (1, tg), B' = (tg, 1): out = A'.*v + B'.*q  (2 ops)
        const ull A = pack2(1.f, tg);
        const ull B = pack2(tg, 1.f);
        #pragma unroll
        for (int k = 0; k < 16; ++k) {
            ull qr = shflx2(sr[k], msk);
            ull qi = shflx2(si[k], msk);
            sr[k] = ffma2u(A, sr[k], fmul2u(B, qr));
            si[k] = ffma2u(A, si[k], fmul2u(B, qi));
        }
    } else {
        const ull st2 = bc2u(tg);
        #pragma unroll
        for (int k = 0; k < 16; ++k) {
            ull qr = shflx2(sr[k], msk);
            ull qi = shflx2(si[k], msk);
            const bool ctl = (k >> (Bc - 1)) & 1;       // compile-time after unroll
            // ctl=0: v + t q ; ctl=1: t v + q  (operand swap, 1 fma)
            sr[k] = ctl ? ffma2u(st2, sr[k], qr) : ffma2u(st2, qr, sr[k]);
            si[k] = ctl ? ffma2u(st2, si[k], qi) : ffma2u(st2, qi, si[k]);
        }
    }
}

// ---------------------------------------------------------------------------
// Standalone CNOT: local control bit BC (>=1), local/comp target BT.
// ---------------------------------------------------------------------------
template<int L, int BC, int BT>
__device__ __forceinline__ void cnot_gate(ull sr[16], ull si[16], int lane) {
    if constexpr (BC >= 1 && BT >= 1) {
        constexpr int pbc = BC - 1, pbt = BT - 1;
        #pragma unroll
        for (int k = 0; k < 16; ++k) {
            if (((k >> pbc) & 1) && !((k >> pbt) & 1)) {
                const int k2 = k | (1 << pbt);
                ull t;
                t = sr[k]; sr[k] = sr[k2]; sr[k2] = t;
                t = si[k]; si[k] = si[k2]; si[k2] = t;
            }
        }
    } else {   // BC >= 1, BT == 0
        constexpr int pb = BC - 1;
        #pragma unroll
        for (int k = 0; k < 16; ++k) {
            if ((k >> pb) & 1) {
                sr[k] = swap2(sr[k]);
                si[k] = swap2(si[k]);
            }
        }
    }
}

// fused diagonal: per pack complex multiply by table phase.
// 16 INDEPENDENT loads — ptxas front-batches them (MLP ~16). Do NOT chain
// them through one register ("prefetch"): that serializes the loads (R11).
__device__ __forceinline__ void apply_diag(ull sr[16], ull si[16], int lane,
                                           const float4* __restrict__ tbl) {
    const ulonglong2* t2 = reinterpret_cast<const ulonglong2*>(tbl);
    #pragma unroll
    for (int k = 0; k < 16; ++k) {
        ulonglong2 t = __ldg(t2 + k * 32 + lane);
        ull c = t.x, s = t.y;
        ull r = sr[k], i = si[k];
        sr[k] = fsub2u(fmul2u(c, r), fmul2u(s, i));
        si[k] = ffma2u(c, i, fmul2u(s, r));
    }
}

// ---------------------------------------------------------------------------
// Block L (shift r = L): see R10 schedule comments.
// ---------------------------------------------------------------------------
template<int L, int W>
__device__ __forceinline__ void standalone_taus(ull sr[16], ull si[16], int lane) {
    if constexpr (W <= 9 - L) {
        cnot_gate<L, 9 - W, 9 - W - L>(sr, si, lane);
        standalone_taus<L, W + 1>(sr, si, lane);
    }
}
template<int L, int W>
__device__ __forceinline__ void fused_stages(ull sr[16], ull si[16], int lane,
                                             const float2* __restrict__ ry) {
    if constexpr (W <= 9) {
        constexpr int Bc = 9 - W;          // local control bit (0..L-1)
        constexpr int B5 = 14 - W - L;     // logical lane-space target bit (0..4)
        fused_cnot_ry<L, Bc, B5>(sr, si, lane, __ldg(ry + (W + L - 10)));
        fused_stages<L, W + 1>(sr, si, lane, ry);
    }
}
template<int L, int Q>
__device__ __forceinline__ void remaining_gates(ull sr[16], ull si[16], int lane,
                                                const float2* __restrict__ ry) {
    if constexpr (Q <= 9) {
        if constexpr (Q <= 4) {
            ry_lane_gate<L, 4 - Q>(sr, si, lane, __ldg(ry + Q));
        } else {
            constexpr int B = 9 - Q;
            if constexpr (L <= 4 && B >= 4 - L)
                ry_local_gate_fused<L, B>(sr, si, lane, __ldg(ry + Q));
            else
                ry_local_gate<B>(sr, si, __ldg(ry + Q));
        }
        remaining_gates<L, Q + 1>(sr, si, lane, ry);
    }
}
template<int L>
__device__ __forceinline__ void fused_layer(ull sr[16], ull si[16], int lane) {
    apply_diag(sr, si, lane, g_E[L - 1]);
    standalone_taus<L, 5>(sr, si, lane);       // local/local only
    fused_stages<L, 10 - L>(sr, si, lane, g_ry[L]);
    remaining_gates<L, L>(sr, si, lane, g_ry[L]);
}

// ---------------------------------------------------------------------------
// Main kernel: one warp per sample; 256 thr, 2 CTAs/SM (~126 regs, no spill).
// ---------------------------------------------------------------------------
__global__ void __launch_bounds__(256, 2) qcnn_kernel(
    const float* __restrict__ x,
    const float* __restrict__ fc_b,
    float* __restrict__ out)
{
    const int warp = (blockIdx.x * blockDim.x + threadIdx.x) >> 5;
    const int lane = threadIdx.x & 31;
    if (warp >= BATCH) return;

    // --- initial product state magnitudes (Λ = identity here) ---------------
    const float* xb = x + warp * NQ;
    float cq[NQ], sq[NQ];
    #pragma unroll
    for (int q = 0; q < NQ; ++q) {
        float h = 0.5f * __ldg(xb + q);
        __sincosf(h, &sq[q], &cq[q]);
    }
    float A = 1.f;
    #pragma unroll
    for (int q = 0; q < 5; ++q)
        A *= ((lane >> (4 - q)) & 1) ? sq[q] : cq[q];

    float m[16];
    m[0] = A;
    #pragma unroll
    for (int t = 0; t < 4; ++t) {
        const int q = 8 - t;
        const int sz = 1 << t;
        #pragma unroll
        for (int k = sz - 1; k >= 0; --k) {
            float v = m[k];
            m[k + sz] = v * sq[q];
            m[k]      = v * cq[q];
        }
    }
    ull sr[16], si[16];
    {
        const ulonglong2* t2 = reinterpret_cast<const ulonglong2*>(g_T0);
        #pragma unroll
        for (int k = 0; k < 16; ++k) {
            ulonglong2 t = __ldg(t2 + k * 32 + lane);
            ull mag2 = pack2(m[k] * cq[9], m[k] * sq[9]);
            sr[k] = fmul2u(mag2, t.x);
            si[k] = fmul2u(mag2, t.y);
        }
    }

    // --- circuit -------------------------------------------------------------
    remaining_gates<0, 0>(sr, si, lane, g_ry[0]);   // Y_0 (+ fused tau of block 1)
    fused_layer<1>(sr, si, lane);
    fused_layer<2>(sr, si, lane);
    fused_layer<3>(sr, si, lane);
    fused_layer<4>(sr, si, lane);
    fused_layer<5>(sr, si, lane);
    // P_5 (r=6) and Λ_5 fully virtualized into the epilogue weight table.

    // --- epilogue: out = sum_m w_m |psi_m|^2; w carries (Πcos)^2 scale -------
    const ull* wtab = reinterpret_cast<const ull*>(g_W);
    ull acc2 = pack2(0.f, 0.f);
    #pragma unroll
    for (int k = 0; k < 16; ++k) {
        ull w2 = __ldg(wtab + k * 32 + lane);
        ull p2 = ffma2u(si[k], si[k], fmul2u(sr[k], sr[k]));
        acc2 = ffma2u(w2, p2, acc2);
    }
    float ax, ay; unpack2(acc2, ax, ay);
    float acc = ax + ay;
    #pragma unroll
    for (int off = 16; off; off >>= 1)
        acc += __shfl_xor_sync(0xffffffffu, acc, off);

    if (lane == 0) out[warp] = acc + __ldg(fc_b);
}

// ---------------------------------------------------------------------------
extern "C" void kernel_launch(void* const* d_in, const int* in_sizes, int n_in,
                              void* d_out, int out_size) {
    const float* x    = (const float*)d_in[0];   // (16384, 10)
    const float* ql   = (const float*)d_in[1];   // (6, 10, 3)
    const float* fcw  = (const float*)d_in[2];   // (1, 10)
    const float* fcb  = (const float*)d_in[3];   // (1,)
    float* out = (float*)d_out;                  // (16384, 1)

    table_kernel<<<7, 512>>>(ql, fcw);
    qcnn_kernel<<<BATCH / 8, 256>>>(x, fcb, out);
}

// round 15
// speedup vs baseline: 2.0142x; 1.0257x over previous
#include <cuda_runtime.h>

#define NQ      10
#define DIM     1024
#define NLAYERS 6
#define BATCH   16384

typedef unsigned long long ull;

// Precomputed tables (sample-independent):
//  g_ry[l][q] = (tan θ/2, cos θ/2)   — gates use .x = t; scale uses cos
//  g_T0[idx]  = init phases, layout (c0, c1, s0, s1)  [c-pack | s-pack]
//  g_E[l-1][idx] = fused diagonal, same layout (Λ-baked + tau-conjugated)
//  g_W[idx]   = epilogue weights (S6^{-1}, Λ_5, and (Πcos)² scale baked)
// idx = k*32 + lane (physical); pair covers local pack k, components 0/1.
// RY gates run in TANGENT form; the global (Π cos)² is folded into g_W.
__device__ float2 g_ry[NLAYERS][NQ];
__device__ __align__(16) float4 g_T0[512];
__device__ __align__(16) float4 g_E[5][512];
__device__ __align__(8)  float2 g_W[512];

// ---------------------------------------------------------------------------
// GF(2) algebra.
// ---------------------------------------------------------------------------
__host__ __device__ constexpr int s6inv_map(int m) {
    for (int w = 0; w < 10; ++w) {
        int cb = 9 - w, tb = 9 - ((w + 6) % 10);
        m ^= ((m >> cb) & 1) << tb;
    }
    return m;
}
__host__ __device__ constexpr int lam_after(int L, int v) {
    for (int l = 1; l <= L; ++l)
        for (int w = 0; w + l <= 4; ++w) {
            int c = 4 - w, t = 4 - w - l;
            v ^= ((v >> c) & 1) << t;
        }
    return v;
}
__host__ __device__ constexpr int inv_mask(int L, int b) {
    for (int v = 1; v < 32; ++v)
        if (lam_after(L, v) == (1 << b)) return v;
    return 0;
}
__host__ __device__ constexpr int row_mask(int L, int b) {
    int r = 0;
    for (int j = 0; j < 5; ++j)
        r |= ((lam_after(L, 1 << j) >> b) & 1) << j;
    return r;
}

// ---------------------------------------------------------------------------
// Packed f32x2 helpers on 64-bit values ("l" constraints keep PTX in .b64).
// ---------------------------------------------------------------------------
__device__ __forceinline__ ull ffma2u(ull a, ull b, ull c) {
    ull d;
    asm("fma.rn.f32x2 %0,%1,%2,%3;" : "=l"(d) : "l"(a), "l"(b), "l"(c));
    return d;
}
__device__ __forceinline__ ull fmul2u(ull a, ull b) {
    ull d;
    asm("mul.rn.f32x2 %0,%1,%2;" : "=l"(d) : "l"(a), "l"(b));
    return d;
}
__device__ __forceinline__ ull fsub2u(ull a, ull b) {
    ull d;
    asm("sub.rn.f32x2 %0,%1,%2;" : "=l"(d) : "l"(a), "l"(b));
    return d;
}
__device__ __forceinline__ ull pack2(float x, float y) {
    ull d;
    asm("mov.b64 %0,{%1,%2};" : "=l"(d) : "f"(x), "f"(y));
    return d;
}
__device__ __forceinline__ void unpack2(ull v, float& x, float& y) {
    asm("mov.b64 {%0,%1},%2;" : "=f"(x), "=f"(y) : "l"(v));
}
__device__ __forceinline__ ull bc2u(float v) { return pack2(v, v); }
__device__ __forceinline__ ull swap2(ull v) {
    float x, y; unpack2(v, x, y); return pack2(y, x);
}
__device__ __forceinline__ ull shflx2(ull v, unsigned msk) {
    float x, y; unpack2(v, x, y);
    x = __shfl_xor_sync(0xffffffffu, x, msk);
    y = __shfl_xor_sync(0xffffffffu, y, msk);
    return pack2(x, y);
}

// ---------------------------------------------------------------------------
// Pre-kernel: one job per block. Job 0: g_ry + T0; jobs 1..5: E_l; job 6: W.
// ---------------------------------------------------------------------------
__device__ __forceinline__ float sum_signed(int n, const float* ql, int l, int off) {
    float a = 0.f;
    #pragma unroll
    for (int q = 0; q < NQ; ++q) {
        float v = ql[(l * NQ + q) * 3 + off];
        a += ((n >> (9 - q)) & 1) ? v : -v;
    }
    return 0.5f * a;
}

__global__ void table_kernel(const float* __restrict__ ql,
                             const float* __restrict__ fcw) {
    const int idx = threadIdx.x;      // 0..511
    const int job = blockIdx.x;       // 0..6
    const int k = idx >> 5, lane = idx & 31;

    if (job == 0) {
        if (idx < NLAYERS * NQ) {
            int l = idx / NQ, q = idx % NQ;
            float s, c; sincosf(0.5f * ql[(l * NQ + q) * 3 + 1], &s, &c);
            g_ry[l][q] = make_float2(s / c, c);   // (tan, cos)
        }
        // T0 (Λ = identity): (-i)^popc(n) * Dphi_0[n]; layout (c0,c1,s0,s1)
        float cs[2], sn[2];
        #pragma unroll
        for (int comp = 0; comp < 2; ++comp) {
            int n = (lane << 5) | (k << 1) | comp;
            float ang = -1.57079632679f * __popc(n) + sum_signed(n, ql, 0, 0);
            sincosf(ang, &sn[comp], &cs[comp]);
        }
        g_T0[idx] = make_float4(cs[0], cs[1], sn[0], sn[1]);
    } else if (job <= 5) {
        // E_l, Λ_{l-1}-baked, conjugated past the moved lane-ctl taus of
        // block l: E'[p,j] = E[p, j ^ f(p)]. Layout (c0,c1,s0,s1).
        const int l = job;
        int llog = lam_after(l - 1, lane);
        int f = 0;
        for (int w = 5 - l; w <= 4; ++w)
            if (__popc(lane & row_mask(l, 4 - w)) & 1) f ^= 1 << (9 - w - l);
        float cs[2], sn[2];
        #pragma unroll
        for (int comp = 0; comp < 2; ++comp) {
            int n = ((llog << 5) | (k << 1) | comp) ^ f;
            float angw = sum_signed(n, ql, l - 1, 2);
            int p = n;             // sigma^{-1}: apply tau_0 .. tau_9 in order
            #pragma unroll
            for (int w = 0; w < NQ; ++w) {
                int cbit = 9 - w;
                int tbit = 9 - ((w + l) % NQ);
                p ^= ((p >> cbit) & 1) << tbit;
            }
            float angp = sum_signed(p, ql, l, 0);
            sincosf(angw + angp, &sn[comp], &cs[comp]);
        }
        g_E[l - 1][idx] = make_float4(cs[0], cs[1], sn[0], sn[1]);
    } else {
        // Epilogue weights with Λ_5, S6^{-1}, and (Π cos)^2 scale baked.
        float sc = 1.f;
        #pragma unroll 1
        for (int i = 0; i < NLAYERS * NQ; ++i)
            sc *= cosf(0.5f * ql[i * 3 + 1]);
        const float sc2 = sc * sc;
        int llog = lam_after(5, lane);
        float wv[2];
        #pragma unroll
        for (int comp = 0; comp < 2; ++comp) {
            int n = (llog << 5) | (k << 1) | comp;
            int p = s6inv_map(n);
            float a = 0.f;
            #pragma unroll
            for (int q = 0; q < NQ; ++q) {
                float v = fcw[q];
                a += ((p >> (9 - q)) & 1) ? -v : v;
            }
            wv[comp] = a * sc2;
        }
        g_W[idx] = make_float2(wv[0], wv[1]);
    }
}

// ---------------------------------------------------------------------------
// State layout: logical amplitude n: bits 9..5 lane (via Λ), 4..1 pack k,
// 0 comp (low/high float of the ull). Qubit q acts on logical bit 9-q.
// All RY gates in tangent form; global cos product deferred into g_W.
// ---------------------------------------------------------------------------

// RY gate on logical lane-space bit B5 (layer-block context L for Λ).
template<int L, int B5>
__device__ __forceinline__ void ry_lane_gate(ull sr[16], ull si[16], int lane,
                                             float2 g) {
    constexpr unsigned msk = (unsigned)inv_mask(L, B5);
    constexpr int row = row_mask(L, B5);
    const bool hi = __popc(lane & row) & 1;
    const ull st2 = bc2u(hi ? g.x : -g.x);       // ± tan
    #pragma unroll
    for (int k = 0; k < 16; ++k) {
        ull qr = shflx2(sr[k], msk);
        ull qi = shflx2(si[k], msk);
        sr[k] = ffma2u(st2, qr, sr[k]);          // v + (±t) q
        si[k] = ffma2u(st2, qi, si[k]);
    }
}

// Plain RY gate on local bit B (1..4 = pack bit B-1; 0 = comp bit).
template<int B>
__device__ __forceinline__ void ry_local_gate(ull sr[16], ull si[16], float2 g) {
    if constexpr (B >= 1) {
        constexpr int pb = B - 1;
        const ull t2 = bc2u(g.x), nt2 = bc2u(-g.x);
        #pragma unroll
        for (int t = 0; t < 8; ++t) {
            const int k  = ((t >> pb) << (pb + 1)) | (t & ((1 << pb) - 1));
            const int k2 = k | (1 << pb);
            ull Ar = sr[k], Ai = si[k], Br = sr[k2], Bi = si[k2];
            sr[k]  = ffma2u(nt2, Br, Ar);        // A - tB
            si[k]  = ffma2u(nt2, Bi, Ai);
            sr[k2] = ffma2u(t2, Ar, Br);         // tA + B
            si[k2] = ffma2u(t2, Ai, Bi);
        }
    } else {
        const ull tp2 = pack2(-g.x, g.x);
        #pragma unroll
        for (int k = 0; k < 16; ++k) {
            sr[k] = ffma2u(tp2, swap2(sr[k]), sr[k]);
            si[k] = ffma2u(tp2, swap2(si[k]), si[k]);
        }
    }
}

// RY local gate on bit B, fused with a FOLLOWING lane-ctl CNOT from block J+1.
// Selection is HOISTED: the four broadcast coefficient packs are chosen once
// per gate (4 SELs), and the inner loop is pure fmul/ffma — zero SELs.
//   out[k]  = α·A + β·B,  out[k2] = γ·A + δ·B
//   ctl=0: (α,β,γ,δ) = (1,−t, t, 1)    [rotation rows in order]
//   ctl=1: (α,β,γ,δ) = (t, 1, 1,−t)    [rows swapped by the CNOT]
template<int J, int B>
__device__ __forceinline__ void ry_local_gate_fused(ull sr[16], ull si[16],
                                                    int lane, float2 g) {
    constexpr int row = row_mask(J + 1, B + J - 4);
    const bool ctl = __popc(lane & row) & 1;
    const float tg = g.x;
    if constexpr (B >= 1) {
        constexpr int pb = B - 1;
        const ull al = bc2u(ctl ? tg : 1.f);
        const ull be = bc2u(ctl ? 1.f : -tg);
        const ull ga = bc2u(ctl ? 1.f : tg);
        const ull de = bc2u(ctl ? -tg : 1.f);
        #pragma unroll
        for (int t = 0; t < 8; ++t) {
            const int k  = ((t >> pb) << (pb + 1)) | (t & ((1 << pb) - 1));
            const int k2 = k | (1 << pb);
            ull Ar = sr[k], Ai = si[k], Br = sr[k2], Bi = si[k2];
            sr[k]  = ffma2u(be, Br, fmul2u(al, Ar));
            si[k]  = ffma2u(be, Bi, fmul2u(al, Ai));
            sr[k2] = ffma2u(de, Br, fmul2u(ga, Ar));
            si[k2] = ffma2u(de, Bi, fmul2u(ga, Ai));
        }
    } else {
        // out = α⊙v + β⊙swap(v);  ctl=0: α=(1,1), β=(−t,t)
        //                          ctl=1: α=(t,−t), β=(1,1)
        const ull al = ctl ? pack2(tg, -tg) : pack2(1.f, 1.f);
        const ull be = ctl ? pack2(1.f, 1.f) : pack2(-tg, tg);
        #pragma unroll
        for (int k = 0; k < 16; ++k) {
            sr[k] = ffma2u(al, sr[k], fmul2u(be, swap2(sr[k])));
            si[k] = ffma2u(al, si[k], fmul2u(be, swap2(si[k])));
        }
    }
}

// Fused stage: CNOT(local control bit Bc -> logical lane bit B5) + RY(target).
template<int L, int Bc, int B5>
__device__ __forceinline__ void fused_cnot_ry(ull sr[16], ull si[16], int lane,
                                              float2 g) {
    constexpr unsigned msk = (unsigned)inv_mask(L, B5);
    constexpr int row = row_mask(L, B5);
    const bool hi = __popc(lane & row) & 1;
    const float tg = hi ? g.x : -g.x;
    if constexpr (Bc == 0) {
        // A' = (1, tg), B' = (tg, 1): out = A'.*v + B'.*q  (2 ops)
        const ull A = pack2(1.f, tg);
        const ull B = pack2(tg, 1.f);
        #pragma unroll
        for (int k = 0; k < 16; ++k) {
            ull qr = shflx2(sr[k], msk);
            ull qi = shflx2(si[k], msk);
            sr[k] = ffma2u(A, sr[k], fmul2u(B, qr));
            si[k] = ffma2u(A, si[k], fmul2u(B, qi));
        }
    } else {
        const ull st2 = bc2u(tg);
        #pragma unroll
        for (int k = 0; k < 16; ++k) {
            ull qr = shflx2(sr[k], msk);
            ull qi = shflx2(si[k], msk);
            const bool ctl = (k >> (Bc - 1)) & 1;       // compile-time after unroll
            // ctl=0: v + t q ; ctl=1: t v + q  (operand swap, 1 fma)
            sr[k] = ctl ? ffma2u(st2, sr[k], qr) : ffma2u(st2, qr, sr[k]);
            si[k] = ctl ? ffma2u(st2, si[k], qi) : ffma2u(st2, qi, si[k]);
        }
    }
}

// ---------------------------------------------------------------------------
// Standalone CNOT: local control bit BC (>=1), local/comp target BT.
// ---------------------------------------------------------------------------
template<int L, int BC, int BT>
__device__ __forceinline__ void cnot_gate(ull sr[16], ull si[16], int lane) {
    if constexpr (BC >= 1 && BT >= 1) {
        constexpr int pbc = BC - 1, pbt = BT - 1;
        #pragma unroll
        for (int k = 0; k < 16; ++k) {
            if (((k >> pbc) & 1) && !((k >> pbt) & 1)) {
                const int k2 = k | (1 << pbt);
                ull t;
                t = sr[k]; sr[k] = sr[k2]; sr[k2] = t;
                t = si[k]; si[k] = si[k2]; si[k2] = t;
            }
        }
    } else {   // BC >= 1, BT == 0
        constexpr int pb = BC - 1;
        #pragma unroll
        for (int k = 0; k < 16; ++k) {
            if ((k >> pb) & 1) {
                sr[k] = swap2(sr[k]);
                si[k] = swap2(si[k]);
            }
        }
    }
}

// fused diagonal: per pack complex multiply by table phase.
// 16 INDEPENDENT loads — ptxas front-batches them (MLP ~16). Do NOT chain
// them through one register ("prefetch"): that serializes the loads (R11).
__device__ __forceinline__ void apply_diag(ull sr[16], ull si[16], int lane,
                                           const float4* __restrict__ tbl) {
    const ulonglong2* t2 = reinterpret_cast<const ulonglong2*>(tbl);
    #pragma unroll
    for (int k = 0; k < 16; ++k) {
        ulonglong2 t = __ldg(t2 + k * 32 + lane);
        ull c = t.x, s = t.y;
        ull r = sr[k], i = si[k];
        sr[k] = fsub2u(fmul2u(c, r), fmul2u(s, i));
        si[k] = ffma2u(c, i, fmul2u(s, r));
    }
}

// ---------------------------------------------------------------------------
// Block L (shift r = L): see R10 schedule comments.
// ---------------------------------------------------------------------------
template<int L, int W>
__device__ __forceinline__ void standalone_taus(ull sr[16], ull si[16], int lane) {
    if constexpr (W <= 9 - L) {
        cnot_gate<L, 9 - W, 9 - W - L>(sr, si, lane);
        standalone_taus<L, W + 1>(sr, si, lane);
    }
}
template<int L, int W>
__device__ __forceinline__ void fused_stages(ull sr[16], ull si[16], int lane,
                                             const float2* __restrict__ ry) {
    if constexpr (W <= 9) {
        constexpr int Bc = 9 - W;          // local control bit (0..L-1)
        constexpr int B5 = 14 - W - L;     // logical lane-space target bit (0..4)
        fused_cnot_ry<L, Bc, B5>(sr, si, lane, __ldg(ry + (W + L - 10)));
        fused_stages<L, W + 1>(sr, si, lane, ry);
    }
}
template<int L, int Q>
__device__ __forceinline__ void remaining_gates(ull sr[16], ull si[16], int lane,
                                                const float2* __restrict__ ry) {
    if constexpr (Q <= 9) {
        if constexpr (Q <= 4) {
            ry_lane_gate<L, 4 - Q>(sr, si, lane, __ldg(ry + Q));
        } else {
            constexpr int B = 9 - Q;
            if constexpr (L <= 4 && B >= 4 - L)
                ry_local_gate_fused<L, B>(sr, si, lane, __ldg(ry + Q));
            else
                ry_local_gate<B>(sr, si, __ldg(ry + Q));
        }
        remaining_gates<L, Q + 1>(sr, si, lane, ry);
    }
}
template<int L>
__device__ __forceinline__ void fused_layer(ull sr[16], ull si[16], int lane) {
    apply_diag(sr, si, lane, g_E[L - 1]);
    standalone_taus<L, 5>(sr, si, lane);       // local/local only
    fused_stages<L, 10 - L>(sr, si, lane, g_ry[L]);
    remaining_gates<L, L>(sr, si, lane, g_ry[L]);
}

// ---------------------------------------------------------------------------
// Main kernel: one warp per sample; 256 thr, 2 CTAs/SM (~126 regs, no spill).
// ---------------------------------------------------------------------------
__global__ void __launch_bounds__(256, 2) qcnn_kernel(
    const float* __restrict__ x,
    const float* __restrict__ fc_b,
    float* __restrict__ out)
{
    const int warp = (blockIdx.x * blockDim.x + threadIdx.x) >> 5;
    const int lane = threadIdx.x & 31;
    if (warp >= BATCH) return;

    // --- initial product state magnitudes (Λ = identity here) ---------------
    const float* xb = x + warp * NQ;
    float cq[NQ], sq[NQ];
    #pragma unroll
    for (int q = 0; q < NQ; ++q) {
        float h = 0.5f * __ldg(xb + q);
        __sincosf(h, &sq[q], &cq[q]);
    }
    float A = 1.f;
    #pragma unroll
    for (int q = 0; q < 5; ++q)
        A *= ((lane >> (4 - q)) & 1) ? sq[q] : cq[q];

    float m[16];
    m[0] = A;
    #pragma unroll
    for (int t = 0; t < 4; ++t) {
        const int q = 8 - t;
        const int sz = 1 << t;
        #pragma unroll
        for (int k = sz - 1; k >= 0; --k) {
            float v = m[k];
            m[k + sz] = v * sq[q];
            m[k]      = v * cq[q];
        }
    }
    ull sr[16], si[16];
    {
        const ulonglong2* t2 = reinterpret_cast<const ulonglong2*>(g_T0);
        #pragma unroll
        for (int k = 0; k < 16; ++k) {
            ulonglong2 t = __ldg(t2 + k * 32 + lane);
            ull mag2 = pack2(m[k] * cq[9], m[k] * sq[9]);
            sr[k] = fmul2u(mag2, t.x);
            si[k] = fmul2u(mag2, t.y);
        }
    }

    // --- circuit -------------------------------------------------------------
    remaining_gates<0, 0>(sr, si, lane, g_ry[0]);   // Y_0 (+ fused tau of block 1)
    fused_layer<1>(sr, si, lane);
    fused_layer<2>(sr, si, lane);
    fused_layer<3>(sr, si, lane);
    fused_layer<4>(sr, si, lane);
    fused_layer<5>(sr, si, lane);
    // P_5 (r=6) and Λ_5 fully virtualized into the epilogue weight table.

    // --- epilogue: out = sum_m w_m |psi_m|^2; w carries (Πcos)^2 scale -------
    const ull* wtab = reinterpret_cast<const ull*>(g_W);
    ull acc2 = pack2(0.f, 0.f);
    #pragma unroll
    for (int k = 0; k < 16; ++k) {
        ull w2 = __ldg(wtab + k * 32 + lane);
        ull p2 = ffma2u(si[k], si[k], fmul2u(sr[k], sr[k]));
        acc2 = ffma2u(w2, p2, acc2);
    }
    float ax, ay; unpack2(acc2, ax, ay);
    float acc = ax + ay;
    #pragma unroll
    for (int off = 16; off; off >>= 1)
        acc += __shfl_xor_sync(0xffffffffu, acc, off);

    if (lane == 0) out[warp] = acc + __ldg(fc_b);
}

// ---------------------------------------------------------------------------
extern "C" void kernel_launch(void* const* d_in, const int* in_sizes, int n_in,
                              void* d_out, int out_size) {
    const float* x    = (const float*)d_in[0];   // (16384, 10)
    const float* ql   = (const float*)d_in[1];   // (6, 10, 3)
    const float* fcw  = (const float*)d_in[2];   // (1, 10)
    const float* fcb  = (const float*)d_in[3];   // (1,)
    float* out = (float*)d_out;                  // (16384, 1)

    table_kernel<<<7, 512>>>(ql, fcw);
    qcnn_kernel<<<BATCH / 8, 256>>>(x, fcb, out);
}

// round 17
// speedup vs baseline: 2.2200x; 1.1022x over previous
#include <cuda_runtime.h>

#define NQ      10
#define DIM     1024
#define NLAYERS 6
#define BATCH   16384

typedef unsigned long long ull;

// Precomputed tables (sample-independent):
//  g_ry[l][q] = (tan θ/2, cos θ/2)
//  g_M[q][0..1] = per-qubit init matrix (layer-0 RY + T0 phases folded):
//      [0] = (m00r, m00i, m01r, m01i), [1] = (m10r, m10i, m11r, m11i)
//      w_q = M_q · (cos x/2, sin x/2);  qubit 5 has t=0 (its layer-0 gate
//      stays in-circuit, fused with block 1's moved tau).
//  g_E[l-1][idx] = fused diagonal, layout (c0,c1,s0,s1) (Λ-baked + tau-conj)
//  g_W[idx]   = epilogue weights (S6^{-1}, Λ_5, (Πcos)² over all 60 gates)
// idx = k*32 + lane (physical).
__device__ float2 g_ry[NLAYERS][NQ];
__device__ __align__(16) float4 g_M[NQ][2];
__device__ __align__(16) float4 g_E[5][512];
__device__ __align__(8)  float2 g_W[512];

// ---------------------------------------------------------------------------
// GF(2) algebra.
// ---------------------------------------------------------------------------
__host__ __device__ constexpr int s6inv_map(int m) {
    for (int w = 0; w < 10; ++w) {
        int cb = 9 - w, tb = 9 - ((w + 6) % 10);
        m ^= ((m >> cb) & 1) << tb;
    }
    return m;
}
__host__ __device__ constexpr int lam_after(int L, int v) {
    for (int l = 1; l <= L; ++l)
        for (int w = 0; w + l <= 4; ++w) {
            int c = 4 - w, t = 4 - w - l;
            v ^= ((v >> c) & 1) << t;
        }
    return v;
}
__host__ __device__ constexpr int inv_mask(int L, int b) {
    for (int v = 1; v < 32; ++v)
        if (lam_after(L, v) == (1 << b)) return v;
    return 0;
}
__host__ __device__ constexpr int row_mask(int L, int b) {
    int r = 0;
    for (int j = 0; j < 5; ++j)
        r |= ((lam_after(L, 1 << j) >> b) & 1) << j;
    return r;
}

// ---------------------------------------------------------------------------
// Packed f32x2 helpers on 64-bit values ("l" constraints keep PTX in .b64).
// ---------------------------------------------------------------------------
__device__ __forceinline__ ull ffma2u(ull a, ull b, ull c) {
    ull d;
    asm("fma.rn.f32x2 %0,%1,%2,%3;" : "=l"(d) : "l"(a), "l"(b), "l"(c));
    return d;
}
__device__ __forceinline__ ull fmul2u(ull a, ull b) {
    ull d;
    asm("mul.rn.f32x2 %0,%1,%2;" : "=l"(d) : "l"(a), "l"(b));
    return d;
}
__device__ __forceinline__ ull fsub2u(ull a, ull b) {
    ull d;
    asm("sub.rn.f32x2 %0,%1,%2;" : "=l"(d) : "l"(a), "l"(b));
    return d;
}
__device__ __forceinline__ ull pack2(float x, float y) {
    ull d;
    asm("mov.b64 %0,{%1,%2};" : "=l"(d) : "f"(x), "f"(y));
    return d;
}
__device__ __forceinline__ void unpack2(ull v, float& x, float& y) {
    asm("mov.b64 {%0,%1},%2;" : "=f"(x), "=f"(y) : "l"(v));
}
__device__ __forceinline__ ull bc2u(float v) { return pack2(v, v); }
__device__ __forceinline__ ull swap2(ull v) {
    float x, y; unpack2(v, x, y); return pack2(y, x);
}
__device__ __forceinline__ ull shflx2(ull v, unsigned msk) {
    float x, y; unpack2(v, x, y);
    x = __shfl_xor_sync(0xffffffffu, x, msk);
    y = __shfl_xor_sync(0xffffffffu, y, msk);
    return pack2(x, y);
}

// ---------------------------------------------------------------------------
// Pre-kernel: one job per block. Job 0: g_ry + g_M; jobs 1..5: E_l; job 6: W.
// ---------------------------------------------------------------------------
__device__ __forceinline__ float sum_signed(int n, const float* ql, int l, int off) {
    float a = 0.f;
    #pragma unroll
    for (int q = 0; q < NQ; ++q) {
        float v = ql[(l * NQ + q) * 3 + off];
        a += ((n >> (9 - q)) & 1) ? v : -v;
    }
    return 0.5f * a;
}

__global__ void table_kernel(const float* __restrict__ ql,
                             const float* __restrict__ fcw) {
    const int idx = threadIdx.x;      // 0..511
    const int job = blockIdx.x;       // 0..6
    const int k = idx >> 5, lane = idx & 31;

    if (job == 0) {
        if (idx < NLAYERS * NQ) {
            int l = idx / NQ, q = idx % NQ;
            float s, c; sincosf(0.5f * ql[(l * NQ + q) * 3 + 1], &s, &c);
            g_ry[l][q] = make_float2(s / c, c);   // (tan, cos)
        }
        // Per-qubit init matrices M_q: layer-0 phases + tangent RY.
        //   u0 = c·e^{-iφ/2}      = c·(cp, -sp)
        //   u1 = (-i)·s·e^{+iφ/2} = s·(sp, -cp)      [the -i from (-i)^popc]
        //   w0 = u0 - t·u1 ; w1 = t·u0 + u1   (t = 0 for qubit 5)
        //   m00 = (cp,-sp); m01 = (-t·sp, t·cp); m10 = (t·cp,-t·sp); m11 = (sp,-cp)
        if (idx < NQ) {
            int q = idx;
            float phi = ql[q * 3 + 0];
            float the = ql[q * 3 + 1];
            float sp, cp; sincosf(0.5f * phi, &sp, &cp);
            float st, ct; sincosf(0.5f * the, &st, &ct);
            float t = (q == 5) ? 0.f : (st / ct);
            g_M[q][0] = make_float4(cp, -sp, -t * sp, t * cp);
            g_M[q][1] = make_float4(t * cp, -t * sp, sp, -cp);
        }
    } else if (job <= 5) {
        // E_l, Λ_{l-1}-baked, conjugated past the moved lane-ctl taus of
        // block l: E'[p,j] = E[p, j ^ f(p)]. Layout (c0,c1,s0,s1).
        const int l = job;
        int llog = lam_after(l - 1, lane);
        int f = 0;
        for (int w = 5 - l; w <= 4; ++w)
            if (__popc(lane & row_mask(l, 4 - w)) & 1) f ^= 1 << (9 - w - l);
        float cs[2], sn[2];
        #pragma unroll
        for (int comp = 0; comp < 2; ++comp) {
            int n = ((llog << 5) | (k << 1) | comp) ^ f;
            float angw = sum_signed(n, ql, l - 1, 2);
            int p = n;             // sigma^{-1}: apply tau_0 .. tau_9 in order
            #pragma unroll
            for (int w = 0; w < NQ; ++w) {
                int cbit = 9 - w;
                int tbit = 9 - ((w + l) % NQ);
                p ^= ((p >> cbit) & 1) << tbit;
            }
            float angp = sum_signed(p, ql, l, 0);
            sincosf(angw + angp, &sn[comp], &cs[comp]);
        }
        g_E[l - 1][idx] = make_float4(cs[0], cs[1], sn[0], sn[1]);
    } else {
        // Epilogue weights with Λ_5, S6^{-1}, and (Π cos)^2 scale baked.
        float sc = 1.f;
        #pragma unroll 1
        for (int i = 0; i < NLAYERS * NQ; ++i)
            sc *= cosf(0.5f * ql[i * 3 + 1]);
        const float sc2 = sc * sc;
        int llog = lam_after(5, lane);
        float wv[2];
        #pragma unroll
        for (int comp = 0; comp < 2; ++comp) {
            int n = (llog << 5) | (k << 1) | comp;
            int p = s6inv_map(n);
            float a = 0.f;
            #pragma unroll
            for (int q = 0; q < NQ; ++q) {
                float v = fcw[q];
                a += ((p >> (9 - q)) & 1) ? -v : v;
            }
            wv[comp] = a * sc2;
        }
        g_W[idx] = make_float2(wv[0], wv[1]);
    }
}

// ---------------------------------------------------------------------------
// State layout: logical amplitude n: bits 9..5 lane (via Λ), 4..1 pack k,
// 0 comp (low/high float of the ull). Qubit q acts on logical bit 9-q.
// All RY gates in tangent form; global cos product deferred into g_W.
// ---------------------------------------------------------------------------

// RY gate on logical lane-space bit B5 (layer-block context L for Λ).
template<int L, int B5>
__device__ __forceinline__ void ry_lane_gate(ull sr[16], ull si[16], int lane,
                                             float2 g) {
    constexpr unsigned msk = (unsigned)inv_mask(L, B5);
    constexpr int row = row_mask(L, B5);
    const bool hi = __popc(lane & row) & 1;
    const ull st2 = bc2u(hi ? g.x : -g.x);       // ± tan
    #pragma unroll
    for (int k = 0; k < 16; ++k) {
        ull qr = shflx2(sr[k], msk);
        ull qi = shflx2(si[k], msk);
        sr[k] = ffma2u(st2, qr, sr[k]);          // v + (±t) q
        si[k] = ffma2u(st2, qi, si[k]);
    }
}

// Plain RY gate on local bit B (1..4 = pack bit B-1; 0 = comp bit).
template<int B>
__device__ __forceinline__ void ry_local_gate(ull sr[16], ull si[16], float2 g) {
    if constexpr (B >= 1) {
        constexpr int pb = B - 1;
        const ull t2 = bc2u(g.x), nt2 = bc2u(-g.x);
        #pragma unroll
        for (int t = 0; t < 8; ++t) {
            const int k  = ((t >> pb) << (pb + 1)) | (t & ((1 << pb) - 1));
            const int k2 = k | (1 << pb);
            ull Ar = sr[k], Ai = si[k], Br = sr[k2], Bi = si[k2];
            sr[k]  = ffma2u(nt2, Br, Ar);        // A - tB
            si[k]  = ffma2u(nt2, Bi, Ai);
            sr[k2] = ffma2u(t2, Ar, Br);         // tA + B
            si[k2] = ffma2u(t2, Ai, Bi);
        }
    } else {
        const ull tp2 = pack2(-g.x, g.x);
        #pragma unroll
        for (int k = 0; k < 16; ++k) {
            sr[k] = ffma2u(tp2, swap2(sr[k]), sr[k]);
            si[k] = ffma2u(tp2, swap2(si[k]), si[k]);
        }
    }
}

// RY local gate on bit B, fused with a FOLLOWING lane-ctl CNOT from block J+1.
// Selection HOISTED (4 SELs per gate, zero in the loop).
template<int J, int B>
__device__ __forceinline__ void ry_local_gate_fused(ull sr[16], ull si[16],
                                                    int lane, float2 g) {
    constexpr int row = row_mask(J + 1, B + J - 4);
    const bool ctl = __popc(lane & row) & 1;
    const float tg = g.x;
    if constexpr (B >= 1) {
        constexpr int pb = B - 1;
        const ull al = bc2u(ctl ? tg : 1.f);
        const ull be = bc2u(ctl ? 1.f : -tg);
        const ull ga = bc2u(ctl ? 1.f : tg);
        const ull de = bc2u(ctl ? -tg : 1.f);
        #pragma unroll
        for (int t = 0; t < 8; ++t) {
            const int k  = ((t >> pb) << (pb + 1)) | (t & ((1 << pb) - 1));
            const int k2 = k | (1 << pb);
            ull Ar = sr[k], Ai = si[k], Br = sr[k2], Bi = si[k2];
            sr[k]  = ffma2u(be, Br, fmul2u(al, Ar));
            si[k]  = ffma2u(be, Bi, fmul2u(al, Ai));
            sr[k2] = ffma2u(de, Br, fmul2u(ga, Ar));
            si[k2] = ffma2u(de, Bi, fmul2u(ga, Ai));
        }
    } else {
        const ull al = ctl ? pack2(tg, -tg) : pack2(1.f, 1.f);
        const ull be = ctl ? pack2(1.f, 1.f) : pack2(-tg, tg);
        #pragma unroll
        for (int k = 0; k < 16; ++k) {
            sr[k] = ffma2u(al, sr[k], fmul2u(be, swap2(sr[k])));
            si[k] = ffma2u(al, si[k], fmul2u(be, swap2(si[k])));
        }
    }
}

// Fused stage: CNOT(local control bit Bc -> logical lane bit B5) + RY(target).
template<int L, int Bc, int B5>
__device__ __forceinline__ void fused_cnot_ry(ull sr[16], ull si[16], int lane,
                                              float2 g) {
    constexpr unsigned msk = (unsigned)inv_mask(L, B5);
    constexpr int row = row_mask(L, B5);
    const bool hi = __popc(lane & row) & 1;
    const float tg = hi ? g.x : -g.x;
    if constexpr (Bc == 0) {
        const ull A = pack2(1.f, tg);
        const ull B = pack2(tg, 1.f);
        #pragma unroll
        for (int k = 0; k < 16; ++k) {
            ull qr = shflx2(sr[k], msk);
            ull qi = shflx2(si[k], msk);
            sr[k] = ffma2u(A, sr[k], fmul2u(B, qr));
            si[k] = ffma2u(A, si[k], fmul2u(B, qi));
        }
    } else {
        const ull st2 = bc2u(tg);
        #pragma unroll
        for (int k = 0; k < 16; ++k) {
            ull qr = shflx2(sr[k], msk);
            ull qi = shflx2(si[k], msk);
            const bool ctl = (k >> (Bc - 1)) & 1;       // compile-time after unroll
            sr[k] = ctl ? ffma2u(st2, sr[k], qr) : ffma2u(st2, qr, sr[k]);
            si[k] = ctl ? ffma2u(st2, si[k], qi) : ffma2u(st2, qi, si[k]);
        }
    }
}

// ---------------------------------------------------------------------------
// Standalone CNOT: local control bit BC (>=1), local/comp target BT.
// ---------------------------------------------------------------------------
template<int L, int BC, int BT>
__device__ __forceinline__ void cnot_gate(ull sr[16], ull si[16], int lane) {
    if constexpr (BC >= 1 && BT >= 1) {
        constexpr int pbc = BC - 1, pbt = BT - 1;
        #pragma unroll
        for (int k = 0; k < 16; ++k) {
            if (((k >> pbc) & 1) && !((k >> pbt) & 1)) {
                const int k2 = k | (1 << pbt);
                ull t;
                t = sr[k]; sr[k] = sr[k2]; sr[k2] = t;
                t = si[k]; si[k] = si[k2]; si[k2] = t;
            }
        }
    } else {   // BC >= 1, BT == 0
        constexpr int pb = BC - 1;
        #pragma unroll
        for (int k = 0; k < 16; ++k) {
            if ((k >> pb) & 1) {
                sr[k] = swap2(sr[k]);
                si[k] = swap2(si[k]);
            }
        }
    }
}

// fused diagonal: 16 INDEPENDENT loads (MLP ~16 — no chained "prefetch", R11).
__device__ __forceinline__ void apply_diag(ull sr[16], ull si[16], int lane,
                                           const float4* __restrict__ tbl) {
    const ulonglong2* t2 = reinterpret_cast<const ulonglong2*>(tbl);
    #pragma unroll
    for (int k = 0; k < 16; ++k) {
        ulonglong2 t = __ldg(t2 + k * 32 + lane);
        ull c = t.x, s = t.y;
        ull r = sr[k], i = si[k];
        sr[k] = fsub2u(fmul2u(c, r), fmul2u(s, i));
        si[k] = ffma2u(c, i, fmul2u(s, r));
    }
}

// ---------------------------------------------------------------------------
// Block L (shift r = L): see R10 schedule comments.
// ---------------------------------------------------------------------------
template<int L, int W>
__device__ __forceinline__ void standalone_taus(ull sr[16], ull si[16], int lane) {
    if constexpr (W <= 9 - L) {
        cnot_gate<L, 9 - W, 9 - W - L>(sr, si, lane);
        standalone_taus<L, W + 1>(sr, si, lane);
    }
}
template<int L, int W>
__device__ __forceinline__ void fused_stages(ull sr[16], ull si[16], int lane,
                                             const float2* __restrict__ ry) {
    if constexpr (W <= 9) {
        constexpr int Bc = 9 - W;          // local control bit (0..L-1)
        constexpr int B5 = 14 - W - L;     // logical lane-space target bit (0..4)
        fused_cnot_ry<L, Bc, B5>(sr, si, lane, __ldg(ry + (W + L - 10)));
        fused_stages<L, W + 1>(sr, si, lane, ry);
    }
}
template<int L, int Q>
__device__ __forceinline__ void remaining_gates(ull sr[16], ull si[16], int lane,
                                                const float2* __restrict__ ry) {
    if constexpr (Q <= 9) {
        if constexpr (Q <= 4) {
            ry_lane_gate<L, 4 - Q>(sr, si, lane, __ldg(ry + Q));
        } else {
            constexpr int B = 9 - Q;
            if constexpr (L <= 4 && B >= 4 - L)
                ry_local_gate_fused<L, B>(sr, si, lane, __ldg(ry + Q));
            else
                ry_local_gate<B>(sr, si, __ldg(ry + Q));
        }
        remaining_gates<L, Q + 1>(sr, si, lane, ry);
    }
}
template<int L>
__device__ __forceinline__ void fused_layer(ull sr[16], ull si[16], int lane) {
    apply_diag(sr, si, lane, g_E[L - 1]);
    standalone_taus<L, 5>(sr, si, lane);       // local/local only
    fused_stages<L, 10 - L>(sr, si, lane, g_ry[L]);
    remaining_gates<L, L>(sr, si, lane, g_ry[L]);
}

// ---------------------------------------------------------------------------
// Main kernel: one warp per sample; 256 thr, 2 CTAs/SM.
// Layer 0 (all single-qubit ops on a product state) is absorbed into the
// init: per-qubit complex 2-vectors w_q = M_q (cos, sin), complex product.
// Only qubit 5's layer-0 gate stays in-circuit (fused with block 1's tau).
// ---------------------------------------------------------------------------
__global__ void __launch_bounds__(256, 2) qcnn_kernel(
    const float* __restrict__ x,
    const float* __restrict__ fc_b,
    float* __restrict__ out)
{
    const int warp = (blockIdx.x * blockDim.x + threadIdx.x) >> 5;
    const int lane = threadIdx.x & 31;
    if (warp >= BATCH) return;

    // --- per-qubit complex 2-vectors after layer-0 absorption ---------------
    const float* xb = x + warp * NQ;
    float w[NQ][4];                 // w0r, w0i, w1r, w1i
    #pragma unroll
    for (int q = 0; q < NQ; ++q) {
        float s, c; __sincosf(0.5f * __ldg(xb + q), &s, &c);
        float4 a = __ldg(&g_M[q][0]);
        float4 b = __ldg(&g_M[q][1]);
        w[q][0] = a.x * c + a.z * s;  w[q][1] = a.y * c + a.w * s;
        w[q][2] = b.x * c + b.z * s;  w[q][3] = b.y * c + b.w * s;
    }

    // lane scalar: A = prod_{q=0..4} w_q[bit_{4-q}(lane)]   (complex)
    float Ar, Ai;
    {
        bool b0 = (lane >> 4) & 1;
        Ar = b0 ? w[0][2] : w[0][0];
        Ai = b0 ? w[0][3] : w[0][1];
        #pragma unroll
        for (int q = 1; q < 5; ++q) {
            bool bq = (lane >> (4 - q)) & 1;
            float wr = bq ? w[q][2] : w[q][0];
            float wi = bq ? w[q][3] : w[q][1];
            float nr = Ar * wr - Ai * wi;
            Ai = Ar * wi + Ai * wr;
            Ar = nr;
        }
    }

    // pack doubling over qubits 8,7,6,5 (pack bits 0..3), complex
    float mr[16], mi[16];
    mr[0] = Ar; mi[0] = Ai;
    #pragma unroll
    for (int t = 0; t < 4; ++t) {
        const int q = 8 - t;
        const int sz = 1 << t;
        #pragma unroll
        for (int k = sz - 1; k >= 0; --k) {
            float r = mr[k], i = mi[k];
            mr[k + sz] = r * w[q][2] - i * w[q][3];
            mi[k + sz] = r * w[q][3] + i * w[q][2];
            mr[k]      = r * w[q][0] - i * w[q][1];
            mi[k]      = r * w[q][1] + i * w[q][0];
        }
    }

    // comp qubit 9: amp(k, comp) = M_k * w9[comp]
    ull sr[16], si[16];
    {
        const ull W9r = pack2(w[9][0], w[9][2]);
        const ull W9i = pack2(w[9][1], w[9][3]);
        #pragma unroll
        for (int k = 0; k < 16; ++k) {
            ull R = bc2u(mr[k]), I = bc2u(mi[k]);
            sr[k] = fsub2u(fmul2u(R, W9r), fmul2u(I, W9i));
            si[k] = ffma2u(R, W9i, fmul2u(I, W9r));
        }
    }

    // --- circuit -------------------------------------------------------------
    // layer 0 remainder: qubit 5's gate, fused with block 1's moved tau
    ry_local_gate_fused<0, 4>(sr, si, lane, __ldg(&g_ry[0][5]));
    fused_layer<1>(sr, si, lane);
    fused_layer<2>(sr, si, lane);
    fused_layer<3>(sr, si, lane);
    fused_layer<4>(sr, si, lane);
    fused_layer<5>(sr, si, lane);
    // P_5 (r=6) and Λ_5 fully virtualized into the epilogue weight table.

    // --- epilogue: out = sum_m w_m |psi_m|^2; w carries (Πcos)^2 scale -------
    const ull* wtab = reinterpret_cast<const ull*>(g_W);
    ull acc2 = pack2(0.f, 0.f);
    #pragma unroll
    for (int k = 0; k < 16; ++k) {
        ull w2 = __ldg(wtab + k * 32 + lane);
        ull p2 = ffma2u(si[k], si[k], fmul2u(sr[k], sr[k]));
        acc2 = ffma2u(w2, p2, acc2);
    }
    float ax, ay; unpack2(acc2, ax, ay);
    float acc = ax + ay;
    #pragma unroll
    for (int off = 16; off; off >>= 1)
        acc += __shfl_xor_sync(0xffffffffu, acc, off);

    if (lane == 0) out[warp] = acc + __ldg(fc_b);
}

// ---------------------------------------------------------------------------
extern "C" void kernel_launch(void* const* d_in, const int* in_sizes, int n_in,
                              void* d_out, int out_size) {
    const float* x    = (const float*)d_in[0];   // (16384, 10)
    const float* ql   = (const float*)d_in[1];   // (6, 10, 3)
    const float* fcw  = (const float*)d_in[2];   // (1, 10)
    const float* fcb  = (const float*)d_in[3];   // (1,)
    float* out = (float*)d_out;                  // (16384, 1)

    table_kernel<<<7, 512>>>(ql, fcw);
    qcnn_kernel<<<BATCH / 8, 256>>>(x, fcb, out);
}